// round 6
// baseline (speedup 1.0000x reference)
#include <cuda_runtime.h>
#include <cuda_bf16.h>
#include <cstdint>
#include <cstddef>

// ---------------------------------------------------------------------------
// Show-Attend-Tell decoder. Round 6:
//  - templated 3xBF16 GEMM: 128x128 tiles (big GEMMs) + 64x128 tiles (step
//    GEMMs -> 2x CTA count on hall/gates/fc)
//  - fused embed+scores+softmax+context kernel (1 launch instead of 3)
// ---------------------------------------------------------------------------

constexpr int B    = 128;
constexpr int P    = 196;
constexpr int ENC  = 2048;
constexpr int EMB  = 512;
constexpr int DEC  = 512;
constexpr int ATT  = 512;
constexpr int VOC  = 10000;
constexpr int T    = 20;
constexpr int NSTEP = T - 1;           // 19
constexpr int G4   = 4 * DEC;          // 2048
constexpr int HALLN = ATT + ENC + G4;  // 4608
constexpr int XDIM = EMB + ENC;        // 2560
constexpr int KSPLIT = 8;
constexpr int KCHUNK = XDIM / KSPLIT;  // 320

using bf16 = __nv_bfloat16;

// ----------------------------- device scratch ------------------------------
__device__ float g_hc[B * 2 * DEC];
__device__ float g_c[B * DEC];
__device__ __align__(16) bf16  g_h_h[B * DEC];
__device__ __align__(16) bf16  g_h_l[B * DEC];
__device__ __align__(16) bf16  g_mean_h[B * ENC];
__device__ __align__(16) bf16  g_mean_l[B * ENC];
__device__ __align__(16) bf16  g_x_h[B * XDIM];
__device__ __align__(16) bf16  g_x_l[B * XDIM];
__device__ __align__(16) bf16  g_E_h[(size_t)B * P * ENC];   // enc_out hi
__device__ __align__(16) bf16  g_E_l[(size_t)B * P * ENC];   // enc_out lo
__device__ float g_encproj[(size_t)B * P * ATT];   // fp32 (softmax path)
__device__ float g_hall[B * HALLN];
__device__ float g_gpart[(size_t)KSPLIT * B * G4];
// packed / transposed weights (bf16 hi/lo planes, [N][K] layout)
__device__ __align__(16) bf16 g_WencT_h[ATT * ENC];
__device__ __align__(16) bf16 g_WencT_l[ATT * ENC];
__device__ __align__(16) bf16 g_WinitT_h[2 * DEC * ENC];
__device__ __align__(16) bf16 g_WinitT_l[2 * DEC * ENC];
__device__ __align__(16) bf16 g_WallT_h[HALLN * DEC];
__device__ __align__(16) bf16 g_WallT_l[HALLN * DEC];
__device__ __align__(16) bf16 g_WihT_h[G4 * XDIM];
__device__ __align__(16) bf16 g_WihT_l[G4 * XDIM];
__device__ __align__(16) bf16 g_WfcT_h[VOC * DEC];
__device__ __align__(16) bf16 g_WfcT_l[VOC * DEC];
__device__ float g_ball[HALLN];
__device__ float g_binit[2 * DEC];

// ------------------------------ helpers -------------------------------------
__device__ __forceinline__ void splitbf(float x, bf16& h, bf16& l) {
    h = __float2bfloat16(x);
    l = __float2bfloat16(x - __bfloat162float(h));
}

__device__ __forceinline__ void mma_bf16(float c[4], const uint32_t a[4],
                                         const uint32_t b[2]) {
    asm volatile(
        "mma.sync.aligned.m16n8k16.row.col.f32.bf16.bf16.f32 "
        "{%0,%1,%2,%3}, {%4,%5,%6,%7}, {%8,%9}, {%0,%1,%2,%3};"
        : "+f"(c[0]), "+f"(c[1]), "+f"(c[2]), "+f"(c[3])
        : "r"(a[0]), "r"(a[1]), "r"(a[2]), "r"(a[3]), "r"(b[0]), "r"(b[1]));
}

__device__ __forceinline__ void ldsm4(uint32_t& r0, uint32_t& r1, uint32_t& r2,
                                      uint32_t& r3, uint32_t addr) {
    asm volatile(
        "ldmatrix.sync.aligned.m8n8.x4.shared.b16 {%0,%1,%2,%3}, [%4];"
        : "=r"(r0), "=r"(r1), "=r"(r2), "=r"(r3) : "r"(addr));
}

__device__ __forceinline__ void cpasync16(uint32_t dst, const void* src) {
    asm volatile("cp.async.cg.shared.global [%0], [%1], 16;"
                 :: "r"(dst), "l"(src));
}

// ------------------------------ 3xBF16 GEMM ---------------------------------
// C[M,N] = (Ah+Al)[M,K] @ (Bh+Bl)^T[N,K] (+bias). K-major bf16 operands.
// 3 passes: Ah*Bh + Al*Bh + Ah*Bl. 256 threads = 8 warps (WM x WN), warp tile
// (MT*16) x (NT*8). BM = WM*MT*16, BN = WN*NT*8 = 128. cp.async double buffer,
// ldmatrix.x4, PADK=20 u32 row stride (bank-conflict-free).
// Split-K: z selects [z*kChunk,...), C += z*M*ldc.
// Requires M%BM==0, kChunk%32==0, K%8==0. N tail: B rows clamped, cols guarded.
constexpr int PADK = 20;               // u32 per smem row (16 data + 4 pad)

extern __shared__ uint32_t dynsm[];

template <int WM, int WN, int MT, int NT, int MINB>
__global__ void __launch_bounds__(256, MINB)
gemm_bf3(const bf16* __restrict__ Ah, const bf16* __restrict__ Al,
         const bf16* __restrict__ Bh, const bf16* __restrict__ Bl,
         float* __restrict__ C, int M, int N, int K, int ldc,
         const float* __restrict__ bias, int kChunk) {
    constexpr int BM = WM * MT * 16;
    constexpr int BN = WN * NT * 8;           // 128
    static_assert(WM * WN == 8 && BN == 128, "");
    constexpr int APLANE = BM * PADK;         // u32
    constexpr int BPLANE = BN * PADK;         // u32
    constexpr int STAGE  = 2 * APLANE + 2 * BPLANE;
    constexpr int APT    = BM * 4 / 256;      // 16B chunks per thread (A)

    const int tid  = threadIdx.x;
    const int warp = tid >> 5;
    const int lane = tid & 31;
    const int lr   = lane >> 2;
    const int lq   = lane & 3;
    const int wm   = warp % WM;
    const int wn   = warp / WM;
    const int rowBase = blockIdx.y * BM;
    const int colBase = blockIdx.x * BN;
    const int k0 = blockIdx.z * kChunk;
    const int nIter = kChunk / 32;
    C += (size_t)blockIdx.z * M * ldc;

    const uint32_t smemBase = (uint32_t)__cvta_generic_to_shared(dynsm);

    auto load_stage = [&](int it, int stg) {
        const int kb = k0 + it * 32;
        const uint32_t sb = smemBase + (uint32_t)(stg * STAGE) * 4;
#pragma unroll
        for (int i = 0; i < APT; i++) {
            int idx = tid + i * 256;
            int r = idx >> 2, ch = idx & 3;
            const size_t off = (size_t)(rowBase + r) * K + kb + ch * 8;
            const uint32_t d = (uint32_t)(r * PADK + ch * 4) * 4;
            cpasync16(sb + d,              Ah + off);
            cpasync16(sb + APLANE * 4 + d, Al + off);
        }
#pragma unroll
        for (int i = 0; i < 2; i++) {
            int idx = tid + i * 256;
            int r = idx >> 2, ch = idx & 3;
            const int n = min(colBase + r, N - 1);
            const size_t off = (size_t)n * K + kb + ch * 8;
            const uint32_t d = (uint32_t)(r * PADK + ch * 4) * 4;
            cpasync16(sb + 2u * APLANE * 4 + d,            Bh + off);
            cpasync16(sb + (2u * APLANE + BPLANE) * 4 + d, Bl + off);
        }
    };

    // ldmatrix per-lane address components
    const int aRow = (lane & 7) + ((lane >> 3) & 1) * 8;
    const int aK   = ((lane >> 4) & 1) * 4;
    const int bRow = (lane & 7) + ((lane >> 4) & 1) * 8;
    const int bK   = ((lane >> 3) & 1) * 4;

    float acc[MT][NT][4];
#pragma unroll
    for (int mt = 0; mt < MT; mt++)
#pragma unroll
        for (int nt = 0; nt < NT; nt++)
#pragma unroll
            for (int j = 0; j < 4; j++) acc[mt][nt][j] = 0.f;

    load_stage(0, 0);
    asm volatile("cp.async.commit_group;");

    for (int it = 0; it < nIter; it++) {
        if (it + 1 < nIter) {
            load_stage(it + 1, (it + 1) & 1);
            asm volatile("cp.async.commit_group;");
            asm volatile("cp.async.wait_group 1;");
        } else {
            asm volatile("cp.async.wait_group 0;");
        }
        __syncthreads();

        const uint32_t sb = smemBase + (uint32_t)((it & 1) * STAGE) * 4;
#pragma unroll
        for (int s = 0; s < 2; s++) {
            const uint32_t ks = (uint32_t)(s * 8) * 4;
            uint32_t ah[MT][4], al[MT][4], bh[NT][2], bl[NT][2];
#pragma unroll
            for (int mt = 0; mt < MT; mt++) {
                uint32_t ra = (uint32_t)((wm * MT * 16 + mt * 16 + aRow) *
                                         PADK + aK) * 4 + ks;
                ldsm4(ah[mt][0], ah[mt][1], ah[mt][2], ah[mt][3], sb + ra);
                ldsm4(al[mt][0], al[mt][1], al[mt][2], al[mt][3],
                      sb + APLANE * 4 + ra);
            }
#pragma unroll
            for (int np = 0; np < NT / 2; np++) {
                uint32_t rb = (uint32_t)((wn * NT * 8 + np * 16 + bRow) *
                                         PADK + bK) * 4 + ks;
                ldsm4(bh[2 * np][0], bh[2 * np][1], bh[2 * np + 1][0],
                      bh[2 * np + 1][1], sb + 2u * APLANE * 4 + rb);
                ldsm4(bl[2 * np][0], bl[2 * np][1], bl[2 * np + 1][0],
                      bl[2 * np + 1][1], sb + (2u * APLANE + BPLANE) * 4 + rb);
            }
#pragma unroll
            for (int nt = 0; nt < NT; nt++)
#pragma unroll
                for (int mt = 0; mt < MT; mt++) {
                    mma_bf16(acc[mt][nt], ah[mt], bh[nt]);
                    mma_bf16(acc[mt][nt], al[mt], bh[nt]);
                    mma_bf16(acc[mt][nt], ah[mt], bl[nt]);
                }
        }
        __syncthreads();
    }

    const bool hasBias = (bias != nullptr);
#pragma unroll
    for (int mt = 0; mt < MT; mt++) {
        int r0 = rowBase + wm * MT * 16 + mt * 16 + lr;
#pragma unroll
        for (int nt = 0; nt < NT; nt++) {
            int c0 = colBase + wn * NT * 8 + nt * 8 + 2 * lq;
            float b0 = 0.f, b1 = 0.f;
            if (hasBias) {
                if (c0 < N)     b0 = bias[c0];
                if (c0 + 1 < N) b1 = bias[c0 + 1];
            }
            if (c0 < N) {
                C[(size_t)r0 * ldc + c0] = acc[mt][nt][0] + b0;
                C[(size_t)(r0 + 8) * ldc + c0] = acc[mt][nt][2] + b0;
            }
            if (c0 + 1 < N) {
                C[(size_t)r0 * ldc + c0 + 1] = acc[mt][nt][1] + b1;
                C[(size_t)(r0 + 8) * ldc + c0 + 1] = acc[mt][nt][3] + b1;
            }
        }
    }
}

// Config A (big GEMMs): 128x128 tiles. Config B (step GEMMs): 64x128 tiles.
constexpr int SMEM128 = 2 * (2 * 128 * PADK + 2 * 128 * PADK) * 4;  // 81920
constexpr int SMEM64  = 2 * (2 * 64  * PADK + 2 * 128 * PADK) * 4;  // 61440

// ---------------------------- pack kernels ----------------------------------
constexpr int S0 = ATT * ENC;
constexpr int S1 = 2 * DEC * ENC;
constexpr int S2 = HALLN * DEC;
constexpr int S3 = G4 * XDIM;
constexpr int S4 = VOC * DEC;
constexpr int STOT = S0 + S1 + S2 + S3 + S4;

__global__ void pack_weights(const float* __restrict__ Wenc,
                             const float* __restrict__ Wih_init,
                             const float* __restrict__ Wic_init,
                             const float* __restrict__ Wd,
                             const float* __restrict__ Wf,
                             const float* __restrict__ Whh,
                             const float* __restrict__ Wih,
                             const float* __restrict__ Wfc) {
    int idx = blockIdx.x * 256 + threadIdx.x;
    if (idx >= STOT) return;
    float v; bf16 *dh, *dl; int j = idx;
    if (j < S0) {
        int n = j / ENC, k = j % ENC;
        v = Wenc[(size_t)k * ATT + n];
        dh = &g_WencT_h[j]; dl = &g_WencT_l[j];
    } else if ((j -= S0) < S1) {
        int n = j / ENC, k = j % ENC;
        v = (n < DEC) ? Wih_init[(size_t)k * DEC + n]
                      : Wic_init[(size_t)k * DEC + (n - DEC)];
        dh = &g_WinitT_h[j]; dl = &g_WinitT_l[j];
    } else if ((j -= S1) < S2) {
        int n = j / DEC, k = j % DEC;
        if (n < ATT)            v = Wd[(size_t)k * ATT + n];
        else if (n < ATT + ENC) v = Wf[(size_t)k * ENC + (n - ATT)];
        else                    v = Whh[(size_t)k * G4 + (n - ATT - ENC)];
        dh = &g_WallT_h[j]; dl = &g_WallT_l[j];
    } else if ((j -= S2) < S3) {
        int n = j / XDIM, k = j % XDIM;
        v = Wih[(size_t)k * G4 + n];
        dh = &g_WihT_h[j]; dl = &g_WihT_l[j];
    } else {
        j -= S3;
        int n = j / DEC, k = j % DEC;
        v = Wfc[(size_t)k * VOC + n];
        dh = &g_WfcT_h[j]; dl = &g_WfcT_l[j];
    }
    splitbf(v, *dh, *dl);
}

__global__ void pack_bias(const float* __restrict__ bd,
                          const float* __restrict__ bf,
                          const float* __restrict__ bhh,
                          const float* __restrict__ bih,
                          const float* __restrict__ bh0,
                          const float* __restrict__ bc0) {
    int c = blockIdx.x * 256 + threadIdx.x;
    if (c < HALLN) {
        float v;
        if (c < ATT)            v = bd[c];
        else if (c < ATT + ENC) v = bf[c - ATT];
        else                    v = bhh[c - ATT - ENC] + bih[c - ATT - ENC];
        g_ball[c] = v;
    } else if (c < HALLN + 2 * DEC) {
        int q = c - HALLN;
        g_binit[q] = (q < DEC) ? bh0[q] : bc0[q - DEC];
    }
}

__global__ void split_encout(const float* __restrict__ enc_out) {
    size_t i = (size_t)blockIdx.x * 256 + threadIdx.x;   // float4 index
    float4 v = reinterpret_cast<const float4*>(enc_out)[i];
    bf16 h0, l0, h1, l1, h2, l2, h3, l3;
    splitbf(v.x, h0, l0); splitbf(v.y, h1, l1);
    splitbf(v.z, h2, l2); splitbf(v.w, h3, l3);
    __nv_bfloat162* Eh2 = reinterpret_cast<__nv_bfloat162*>(g_E_h);
    __nv_bfloat162* El2 = reinterpret_cast<__nv_bfloat162*>(g_E_l);
    Eh2[i * 2 + 0] = __nv_bfloat162(h0, h1);
    Eh2[i * 2 + 1] = __nv_bfloat162(h2, h3);
    El2[i * 2 + 0] = __nv_bfloat162(l0, l1);
    El2[i * 2 + 1] = __nv_bfloat162(l2, l3);
}

__global__ void mean_kernel(const float* __restrict__ enc_out) {
    int idx = blockIdx.x * 256 + threadIdx.x;   // B*ENC
    int b = idx / ENC, e = idx % ENC;
    const float* src = enc_out + (size_t)b * P * ENC + e;
    float s = 0.f;
#pragma unroll 4
    for (int p = 0; p < P; p++) s += src[(size_t)p * ENC];
    splitbf(s * (1.f / 196.f), g_mean_h[idx], g_mean_l[idx]);
}

__global__ void split_hc() {
    int idx = blockIdx.x * 256 + threadIdx.x;  // B*DEC
    int b = idx / DEC, d = idx % DEC;
    splitbf(g_hc[b * 2 * DEC + d], g_h_h[idx], g_h_l[idx]);
    g_c[idx] = g_hc[b * 2 * DEC + DEC + d];
}

// -------------------------- fused attention kernel --------------------------
// One block per batch row b:
//   1. embed copy -> x[b, 0:EMB]
//   2. scores[p] = relu(encproj[b,p,:] + dec_att[b,:]) . w_att + b_att
//   3. softmax over p
//   4. context[ch] = sum_p alpha[p] * enc_out[b,p,ch];  x[b,EMB+ch] =
//      sigmoid(fbeta[b,ch]) * context[ch]
__global__ void __launch_bounds__(256)
attention_kernel(const float* __restrict__ enc_out,
                 const float* __restrict__ emb,
                 const int* __restrict__ cap,
                 const float* __restrict__ w_att,
                 const float* __restrict__ b_att, int t) {
    __shared__ float s_dec[ATT];
    __shared__ float s_w[ATT];
    __shared__ float s_sc[P];
    __shared__ float s_al[P];
    __shared__ float red[256];
    const int b = blockIdx.x, tid = threadIdx.x;
    const int warp = tid >> 5, lane = tid & 31;

    // embed copy (tid < 128: 128 float4 = 512 floats)
    if (tid < 128) {
        int cidx = cap[b * T + t];
        float4 v = reinterpret_cast<const float4*>(
            emb + (size_t)cidx * EMB)[tid];
        int o = b * XDIM + tid * 4;
        splitbf(v.x, g_x_h[o + 0], g_x_l[o + 0]);
        splitbf(v.y, g_x_h[o + 1], g_x_l[o + 1]);
        splitbf(v.z, g_x_h[o + 2], g_x_l[o + 2]);
        splitbf(v.w, g_x_h[o + 3], g_x_l[o + 3]);
    }

    for (int i = tid; i < ATT; i += 256) {
        s_dec[i] = g_hall[b * HALLN + i];
        s_w[i]   = w_att[i];
    }
    __syncthreads();

    const float batt = b_att[0];
    for (int p = warp; p < P; p += 8) {
        const float* ep = &g_encproj[((size_t)(b * P + p)) * ATT];
        float s = 0.f;
#pragma unroll 4
        for (int a = lane; a < ATT; a += 32) {
            float e = ep[a] + s_dec[a];
            s += fmaxf(e, 0.f) * s_w[a];
        }
#pragma unroll
        for (int o = 16; o; o >>= 1) s += __shfl_down_sync(0xffffffffu, s, o);
        if (lane == 0) s_sc[p] = s + batt;
    }
    __syncthreads();

    // softmax
    float v = (tid < P) ? s_sc[tid] : -1e30f;
    red[tid] = v;
    __syncthreads();
    for (int o = 128; o; o >>= 1) {
        if (tid < o) red[tid] = fmaxf(red[tid], red[tid + o]);
        __syncthreads();
    }
    float m = red[0];
    __syncthreads();
    float e = (tid < P) ? expf(v - m) : 0.f;
    red[tid] = e;
    __syncthreads();
    for (int o = 128; o; o >>= 1) {
        if (tid < o) red[tid] += red[tid + o];
        __syncthreads();
    }
    if (tid < P) s_al[tid] = e / red[0];
    __syncthreads();

    // context: 2048 channels, 8 per thread (ch = tid + j*256)
    float accv[8];
#pragma unroll
    for (int j = 0; j < 8; j++) accv[j] = 0.f;
    const float* eb = enc_out + (size_t)b * P * ENC;
    for (int p = 0; p < P; p++) {
        const float a = s_al[p];
        const float* row = eb + (size_t)p * ENC + tid;
#pragma unroll
        for (int j = 0; j < 8; j++)
            accv[j] = fmaf(a, row[j * 256], accv[j]);
    }
#pragma unroll
    for (int j = 0; j < 8; j++) {
        const int ch = tid + j * 256;
        float gate = 1.f / (1.f + expf(-g_hall[b * HALLN + ATT + ch]));
        int o = b * XDIM + EMB + ch;
        splitbf(gate * accv[j], g_x_h[o], g_x_l[o]);
    }
}

// Deterministic split-K reduce + LSTM cell; writes h planes + c.
__global__ void lstm_kernel() {
    int idx = blockIdx.x * 256 + threadIdx.x;  // B*DEC
    int b = idx / DEC, d = idx % DEC;
    const float* hallg = &g_hall[b * HALLN + ATT + ENC];
    float gi = hallg[d];
    float gf = hallg[DEC + d];
    float gg = hallg[2 * DEC + d];
    float go = hallg[3 * DEC + d];
#pragma unroll
    for (int s = 0; s < KSPLIT; s++) {
        const float* pp = &g_gpart[((size_t)s * B + b) * G4];
        gi += pp[d];
        gf += pp[DEC + d];
        gg += pp[2 * DEC + d];
        go += pp[3 * DEC + d];
    }
    float c  = g_c[idx];
    float si = 1.f / (1.f + expf(-gi));
    float sf = 1.f / (1.f + expf(-gf));
    float so = 1.f / (1.f + expf(-go));
    float cn = sf * c + si * tanhf(gg);
    float hn = so * tanhf(cn);
    g_c[idx] = cn;
    splitbf(hn, g_h_h[idx], g_h_l[idx]);
}

// ------------------------------- launcher -----------------------------------
extern "C" void kernel_launch(void* const* d_in, const int* in_sizes, int n_in,
                              void* d_out, int out_size) {
    const float* enc_out   = (const float*)d_in[0];
    const int*   captions  = (const int*)  d_in[1];
    const float* emb       = (const float*)d_in[2];
    const float* W_init_h  = (const float*)d_in[3];
    const float* b_init_h  = (const float*)d_in[4];
    const float* W_init_c  = (const float*)d_in[5];
    const float* b_init_c  = (const float*)d_in[6];
    const float* W_enc_att = (const float*)d_in[7];
    const float* b_enc_att = (const float*)d_in[8];
    const float* W_dec_att = (const float*)d_in[9];
    const float* b_dec_att = (const float*)d_in[10];
    const float* w_att     = (const float*)d_in[11];
    const float* b_att     = (const float*)d_in[12];
    const float* W_fbeta   = (const float*)d_in[13];
    const float* b_fbeta   = (const float*)d_in[14];
    const float* W_ih      = (const float*)d_in[15];
    const float* b_ih      = (const float*)d_in[16];
    const float* W_hh      = (const float*)d_in[17];
    const float* b_hh      = (const float*)d_in[18];
    const float* W_fc      = (const float*)d_in[19];
    const float* b_fc      = (const float*)d_in[20];
    float* out = (float*)d_out;

    bf16 *pMh, *pMl, *pHh, *pHl, *pXh, *pXl, *pEh, *pEl;
    bf16 *pWencH, *pWencL, *pWinH, *pWinL, *pWallH, *pWallL,
         *pWihH, *pWihL, *pWfcH, *pWfcL;
    float *p_hc, *p_encproj, *p_hall, *p_gpart, *p_ball, *p_binit;
    cudaGetSymbolAddress((void**)&pEh, g_E_h);
    cudaGetSymbolAddress((void**)&pEl, g_E_l);
    cudaGetSymbolAddress((void**)&pMh, g_mean_h);
    cudaGetSymbolAddress((void**)&pMl, g_mean_l);
    cudaGetSymbolAddress((void**)&pHh, g_h_h);
    cudaGetSymbolAddress((void**)&pHl, g_h_l);
    cudaGetSymbolAddress((void**)&pXh, g_x_h);
    cudaGetSymbolAddress((void**)&pXl, g_x_l);
    cudaGetSymbolAddress((void**)&pWencH, g_WencT_h);
    cudaGetSymbolAddress((void**)&pWencL, g_WencT_l);
    cudaGetSymbolAddress((void**)&pWinH, g_WinitT_h);
    cudaGetSymbolAddress((void**)&pWinL, g_WinitT_l);
    cudaGetSymbolAddress((void**)&pWallH, g_WallT_h);
    cudaGetSymbolAddress((void**)&pWallL, g_WallT_l);
    cudaGetSymbolAddress((void**)&pWihH, g_WihT_h);
    cudaGetSymbolAddress((void**)&pWihL, g_WihT_l);
    cudaGetSymbolAddress((void**)&pWfcH, g_WfcT_h);
    cudaGetSymbolAddress((void**)&pWfcL, g_WfcT_l);
    cudaGetSymbolAddress((void**)&p_hc, g_hc);
    cudaGetSymbolAddress((void**)&p_encproj, g_encproj);
    cudaGetSymbolAddress((void**)&p_hall, g_hall);
    cudaGetSymbolAddress((void**)&p_gpart, g_gpart);
    cudaGetSymbolAddress((void**)&p_ball, g_ball);
    cudaGetSymbolAddress((void**)&p_binit, g_binit);

    auto gemm128 = gemm_bf3<4, 2, 2, 8, 2>;
    auto gemm64  = gemm_bf3<2, 4, 2, 4, 2>;
    cudaFuncSetAttribute(gemm128,
                         cudaFuncAttributeMaxDynamicSharedMemorySize, SMEM128);
    cudaFuncSetAttribute(gemm64,
                         cudaFuncAttributeMaxDynamicSharedMemorySize, SMEM64);

    // ---- one-time precompute (launch #4 = enc_proj GEMM for ncu) ----
    pack_weights<<<(STOT + 255) / 256, 256>>>(W_enc_att, W_init_h, W_init_c,
                                              W_dec_att, W_fbeta, W_hh, W_ih,
                                              W_fc);
    pack_bias<<<(HALLN + 2 * DEC + 255) / 256, 256>>>(b_dec_att, b_fbeta, b_hh,
                                                      b_ih, b_init_h, b_init_c);
    split_encout<<<(int)(((size_t)B * P * ENC / 4 + 255) / 256), 256>>>(enc_out);

    // enc_proj = enc_out @ W_enc_att + b  -> fp32 [25088, 512]
    gemm128<<<dim3(ATT / 128, B * P / 128, 1), 256, SMEM128>>>(
        pEh, pEl, pWencH, pWencL, p_encproj, B * P, ATT, ENC, ATT, b_enc_att,
        ENC);

    mean_kernel<<<B * ENC / 256, 256>>>(enc_out);

    // [h0|c0] = mean @ [W_init_h|W_init_c] + b
    gemm128<<<dim3(2 * DEC / 128, 1, 1), 256, SMEM128>>>(
        pMh, pMl, pWinH, pWinL, p_hc, B, 2 * DEC, ENC, 2 * DEC, p_binit, ENC);
    split_hc<<<B * DEC / 256, 256>>>();

    // ---- decode loop ----
    for (int t = 0; t < NSTEP; t++) {
        // hall = h @ [W_dec_att|W_fbeta|W_hh] + ball    [128, 4608]
        gemm64<<<dim3(HALLN / 128, B / 64, 1), 256, SMEM64>>>(
            pHh, pHl, pWallH, pWallL, p_hall, B, HALLN, DEC, HALLN, p_ball,
            DEC);

        attention_kernel<<<B, 256>>>(enc_out, emb, captions, w_att, b_att, t);

        // gates partials = x @ W_ih, split-K over XDIM
        gemm64<<<dim3(G4 / 128, B / 64, KSPLIT), 256, SMEM64>>>(
            pXh, pXl, pWihH, pWihL, p_gpart, B, G4, XDIM, G4, nullptr, KCHUNK);

        lstm_kernel<<<B * DEC / 256, 256>>>();

        // out[:, t, :] = h_new @ W_fc + b_fc
        gemm64<<<dim3((VOC + 127) / 128, B / 64, 1), 256, SMEM64>>>(
            pHh, pHl, pWfcH, pWfcL, out + (size_t)t * VOC, B, VOC, DEC,
            NSTEP * VOC, b_fc, DEC);
    }
}

// round 7
// speedup vs baseline: 1.2545x; 1.2545x over previous
#include <cuda_runtime.h>
#include <cuda_bf16.h>
#include <cstdint>
#include <cstddef>

// ---------------------------------------------------------------------------
// Show-Attend-Tell decoder. Round 7 (R5 base + merged step GEMMs):
//  - one combined GEMM per step computes fc(t) AND hall(t+1) from h(t)
//    (dual-destination epilogue, 115 CTAs instead of 36+79 serialized)
//  - fused embed+scores+softmax; context stays at 1024 CTAs (R6 lesson)
//  - gates split-K 16 (256 CTAs)
// ---------------------------------------------------------------------------

constexpr int B    = 128;
constexpr int P    = 196;
constexpr int ENC  = 2048;
constexpr int EMB  = 512;
constexpr int DEC  = 512;
constexpr int ATT  = 512;
constexpr int VOC  = 10000;
constexpr int T    = 20;
constexpr int NSTEP = T - 1;           // 19
constexpr int G4   = 4 * DEC;          // 2048
constexpr int HALLN = ATT + ENC + G4;  // 4608
constexpr int COMBN = HALLN + VOC;     // 14608
constexpr int XDIM = EMB + ENC;        // 2560
constexpr int KSPLIT = 16;
constexpr int KCHUNK = XDIM / KSPLIT;  // 160

using bf16 = __nv_bfloat16;

// ----------------------------- device scratch ------------------------------
__device__ float g_hc[B * 2 * DEC];
__device__ float g_c[B * DEC];
__device__ __align__(16) bf16  g_h_h[B * DEC];
__device__ __align__(16) bf16  g_h_l[B * DEC];
__device__ __align__(16) bf16  g_mean_h[B * ENC];
__device__ __align__(16) bf16  g_mean_l[B * ENC];
__device__ __align__(16) bf16  g_x_h[B * XDIM];
__device__ __align__(16) bf16  g_x_l[B * XDIM];
__device__ __align__(16) bf16  g_E_h[(size_t)B * P * ENC];
__device__ __align__(16) bf16  g_E_l[(size_t)B * P * ENC];
__device__ float g_encproj[(size_t)B * P * ATT];
__device__ float g_hall[B * HALLN];
__device__ float g_alpha[B * P];
__device__ float g_gpart[(size_t)KSPLIT * B * G4];
// packed / transposed weights (bf16 hi/lo planes, [N][K] layout)
__device__ __align__(16) bf16 g_WencT_h[ATT * ENC];
__device__ __align__(16) bf16 g_WencT_l[ATT * ENC];
__device__ __align__(16) bf16 g_WinitT_h[2 * DEC * ENC];
__device__ __align__(16) bf16 g_WinitT_l[2 * DEC * ENC];
__device__ __align__(16) bf16 g_WcombT_h[COMBN * DEC];  // [Wall|Wfc]
__device__ __align__(16) bf16 g_WcombT_l[COMBN * DEC];
__device__ __align__(16) bf16 g_WihT_h[G4 * XDIM];
__device__ __align__(16) bf16 g_WihT_l[G4 * XDIM];
__device__ float g_ball[HALLN];
__device__ float g_binit[2 * DEC];

// ------------------------------ helpers -------------------------------------
__device__ __forceinline__ void splitbf(float x, bf16& h, bf16& l) {
    h = __float2bfloat16(x);
    l = __float2bfloat16(x - __bfloat162float(h));
}

__device__ __forceinline__ void mma_bf16(float c[4], const uint32_t a[4],
                                         const uint32_t b[2]) {
    asm volatile(
        "mma.sync.aligned.m16n8k16.row.col.f32.bf16.bf16.f32 "
        "{%0,%1,%2,%3}, {%4,%5,%6,%7}, {%8,%9}, {%0,%1,%2,%3};"
        : "+f"(c[0]), "+f"(c[1]), "+f"(c[2]), "+f"(c[3])
        : "r"(a[0]), "r"(a[1]), "r"(a[2]), "r"(a[3]), "r"(b[0]), "r"(b[1]));
}

__device__ __forceinline__ void ldsm4(uint32_t& r0, uint32_t& r1, uint32_t& r2,
                                      uint32_t& r3, uint32_t addr) {
    asm volatile(
        "ldmatrix.sync.aligned.m8n8.x4.shared.b16 {%0,%1,%2,%3}, [%4];"
        : "=r"(r0), "=r"(r1), "=r"(r2), "=r"(r3) : "r"(addr));
}

__device__ __forceinline__ void cpasync16(uint32_t dst, const void* src) {
    asm volatile("cp.async.cg.shared.global [%0], [%1], 16;"
                 :: "r"(dst), "l"(src));
}

// ------------------------------ 3xBF16 GEMM ---------------------------------
// C[M,N] = (Ah+Al)[M,K] @ (Bh+Bl)^T[N,K]. K-major bf16 operands, 3 passes.
// Block 128x128, BK=32, 256 thr, 8 warps (4Mx2N), warp tile 32x64.
// Dual destination: cols < N1 -> C (ldc, bias); cols >= N1 -> C2 (ldc2, bias2).
// Split-K: z selects [z*kChunk,...), C += z*M*ldc (single-dest use only).
// Requires M%128==0, kChunk%32==0, K%8==0. N tail: B rows clamped, cols guarded.
constexpr int PADK  = 20;
constexpr int PLANE = 128 * PADK;
constexpr int STAGE = 4 * PLANE;
constexpr int GEMM_SMEM = 2 * STAGE * 4;  // 81920 B

extern __shared__ uint32_t dynsm[];

__global__ void __launch_bounds__(256, 2)
gemm_bf3(const bf16* __restrict__ Ah, const bf16* __restrict__ Al,
         const bf16* __restrict__ Bh, const bf16* __restrict__ Bl,
         float* __restrict__ C, float* __restrict__ C2,
         int M, int N, int N1, int K, int ldc, int ldc2,
         const float* __restrict__ bias, const float* __restrict__ bias2,
         int kChunk) {
    const int tid  = threadIdx.x;
    const int warp = tid >> 5;
    const int lane = tid & 31;
    const int lr   = lane >> 2;
    const int lq   = lane & 3;
    const int wm   = warp & 3;
    const int wn   = warp >> 2;
    const int rowBase = blockIdx.y * 128;
    const int colBase = blockIdx.x * 128;
    const int k0 = blockIdx.z * kChunk;
    const int nIter = kChunk / 32;
    C += (size_t)blockIdx.z * M * ldc;

    const uint32_t smemBase = (uint32_t)__cvta_generic_to_shared(dynsm);

    const int tr = tid >> 1;
    const int tc = tid & 1;
    auto load_stage = [&](int it, int stg) {
        const int kb = k0 + it * 32;
        const uint32_t sb = smemBase + (uint32_t)(stg * STAGE) * 4;
        const int nclamp = min(colBase + tr, N - 1);
        const size_t offA = (size_t)(rowBase + tr) * K + kb;
        const size_t offB = (size_t)nclamp * K + kb;
#pragma unroll
        for (int c = 0; c < 2; c++) {
            const int ch = tc * 2 + c;
            const uint32_t d = (uint32_t)(tr * PADK + ch * 4) * 4;
            cpasync16(sb + d,                  Ah + offA + ch * 8);
            cpasync16(sb + PLANE * 4 + d,      Al + offA + ch * 8);
            cpasync16(sb + 2u * PLANE * 4 + d, Bh + offB + ch * 8);
            cpasync16(sb + 3u * PLANE * 4 + d, Bl + offB + ch * 8);
        }
    };

    const int aRow = (lane & 7) + ((lane >> 3) & 1) * 8;
    const int aK   = ((lane >> 4) & 1) * 4;
    const int bRow = (lane & 7) + ((lane >> 4) & 1) * 8;
    const int bK   = ((lane >> 3) & 1) * 4;

    float acc[2][8][4];
#pragma unroll
    for (int mt = 0; mt < 2; mt++)
#pragma unroll
        for (int nt = 0; nt < 8; nt++)
#pragma unroll
            for (int j = 0; j < 4; j++) acc[mt][nt][j] = 0.f;

    load_stage(0, 0);
    asm volatile("cp.async.commit_group;");

    for (int it = 0; it < nIter; it++) {
        if (it + 1 < nIter) {
            load_stage(it + 1, (it + 1) & 1);
            asm volatile("cp.async.commit_group;");
            asm volatile("cp.async.wait_group 1;");
        } else {
            asm volatile("cp.async.wait_group 0;");
        }
        __syncthreads();

        const uint32_t sb = smemBase + (uint32_t)((it & 1) * STAGE) * 4;
#pragma unroll
        for (int s = 0; s < 2; s++) {
            const uint32_t ks = (uint32_t)(s * 8) * 4;
            uint32_t ah[2][4], al[2][4], bh[8][2], bl[8][2];
#pragma unroll
            for (int mt = 0; mt < 2; mt++) {
                uint32_t ra = (uint32_t)((wm * 32 + mt * 16 + aRow) * PADK +
                                         aK) * 4 + ks;
                ldsm4(ah[mt][0], ah[mt][1], ah[mt][2], ah[mt][3], sb + ra);
                ldsm4(al[mt][0], al[mt][1], al[mt][2], al[mt][3],
                      sb + PLANE * 4 + ra);
            }
#pragma unroll
            for (int np = 0; np < 4; np++) {
                uint32_t rb = (uint32_t)((wn * 64 + np * 16 + bRow) * PADK +
                                         bK) * 4 + ks;
                ldsm4(bh[2 * np][0], bh[2 * np][1], bh[2 * np + 1][0],
                      bh[2 * np + 1][1], sb + 2u * PLANE * 4 + rb);
                ldsm4(bl[2 * np][0], bl[2 * np][1], bl[2 * np + 1][0],
                      bl[2 * np + 1][1], sb + 3u * PLANE * 4 + rb);
            }
#pragma unroll
            for (int nt = 0; nt < 8; nt++)
#pragma unroll
                for (int mt = 0; mt < 2; mt++) {
                    mma_bf16(acc[mt][nt], ah[mt], bh[nt]);
                    mma_bf16(acc[mt][nt], al[mt], bh[nt]);
                    mma_bf16(acc[mt][nt], ah[mt], bl[nt]);
                }
        }
        __syncthreads();
    }

#pragma unroll
    for (int mt = 0; mt < 2; mt++) {
        int r0 = rowBase + wm * 32 + mt * 16 + lr;
#pragma unroll
        for (int nt = 0; nt < 8; nt++) {
            int cbase = colBase + wn * 64 + nt * 8 + 2 * lq;
#pragma unroll
            for (int cc = 0; cc < 2; cc++) {
                int c = cbase + cc;
                if (c >= N) continue;
                float v0 = acc[mt][nt][cc];        // row r0
                float v1 = acc[mt][nt][2 + cc];    // row r0+8
                if (c < N1) {
                    float bb = bias ? bias[c] : 0.f;
                    C[(size_t)r0 * ldc + c] = v0 + bb;
                    C[(size_t)(r0 + 8) * ldc + c] = v1 + bb;
                } else {
                    int c2 = c - N1;
                    float bb = bias2 ? bias2[c2] : 0.f;
                    C2[(size_t)r0 * ldc2 + c2] = v0 + bb;
                    C2[(size_t)(r0 + 8) * ldc2 + c2] = v1 + bb;
                }
            }
        }
    }
}

// ---------------------------- pack kernels ----------------------------------
constexpr int S0 = ATT * ENC;            // WencT
constexpr int S1 = 2 * DEC * ENC;        // WinitT
constexpr int S2 = COMBN * DEC;          // WcombT ([Wall|Wfc])
constexpr int S3 = G4 * XDIM;            // WihT
constexpr int STOT = S0 + S1 + S2 + S3;

__global__ void pack_weights(const float* __restrict__ Wenc,
                             const float* __restrict__ Wih_init,
                             const float* __restrict__ Wic_init,
                             const float* __restrict__ Wd,
                             const float* __restrict__ Wf,
                             const float* __restrict__ Whh,
                             const float* __restrict__ Wfc,
                             const float* __restrict__ Wih) {
    int idx = blockIdx.x * 256 + threadIdx.x;
    if (idx >= STOT) return;
    float v; bf16 *dh, *dl; int j = idx;
    if (j < S0) {
        int n = j / ENC, k = j % ENC;
        v = Wenc[(size_t)k * ATT + n];
        dh = &g_WencT_h[j]; dl = &g_WencT_l[j];
    } else if ((j -= S0) < S1) {
        int n = j / ENC, k = j % ENC;
        v = (n < DEC) ? Wih_init[(size_t)k * DEC + n]
                      : Wic_init[(size_t)k * DEC + (n - DEC)];
        dh = &g_WinitT_h[j]; dl = &g_WinitT_l[j];
    } else if ((j -= S1) < S2) {
        int n = j / DEC, k = j % DEC;
        if (n < ATT)            v = Wd[(size_t)k * ATT + n];
        else if (n < ATT + ENC) v = Wf[(size_t)k * ENC + (n - ATT)];
        else if (n < HALLN)     v = Whh[(size_t)k * G4 + (n - ATT - ENC)];
        else                    v = Wfc[(size_t)k * VOC + (n - HALLN)];
        dh = &g_WcombT_h[j]; dl = &g_WcombT_l[j];
    } else {
        j -= S2;
        int n = j / XDIM, k = j % XDIM;
        v = Wih[(size_t)k * G4 + n];
        dh = &g_WihT_h[j]; dl = &g_WihT_l[j];
    }
    splitbf(v, *dh, *dl);
}

__global__ void pack_bias(const float* __restrict__ bd,
                          const float* __restrict__ bf,
                          const float* __restrict__ bhh,
                          const float* __restrict__ bih,
                          const float* __restrict__ bh0,
                          const float* __restrict__ bc0) {
    int c = blockIdx.x * 256 + threadIdx.x;
    if (c < HALLN) {
        float v;
        if (c < ATT)            v = bd[c];
        else if (c < ATT + ENC) v = bf[c - ATT];
        else                    v = bhh[c - ATT - ENC] + bih[c - ATT - ENC];
        g_ball[c] = v;
    } else if (c < HALLN + 2 * DEC) {
        int q = c - HALLN;
        g_binit[q] = (q < DEC) ? bh0[q] : bc0[q - DEC];
    }
}

__global__ void split_encout(const float* __restrict__ enc_out) {
    size_t i = (size_t)blockIdx.x * 256 + threadIdx.x;
    float4 v = reinterpret_cast<const float4*>(enc_out)[i];
    bf16 h0, l0, h1, l1, h2, l2, h3, l3;
    splitbf(v.x, h0, l0); splitbf(v.y, h1, l1);
    splitbf(v.z, h2, l2); splitbf(v.w, h3, l3);
    __nv_bfloat162* Eh2 = reinterpret_cast<__nv_bfloat162*>(g_E_h);
    __nv_bfloat162* El2 = reinterpret_cast<__nv_bfloat162*>(g_E_l);
    Eh2[i * 2 + 0] = __nv_bfloat162(h0, h1);
    Eh2[i * 2 + 1] = __nv_bfloat162(h2, h3);
    El2[i * 2 + 0] = __nv_bfloat162(l0, l1);
    El2[i * 2 + 1] = __nv_bfloat162(l2, l3);
}

__global__ void mean_kernel(const float* __restrict__ enc_out) {
    int idx = blockIdx.x * 256 + threadIdx.x;
    int b = idx / ENC, e = idx % ENC;
    const float* src = enc_out + (size_t)b * P * ENC + e;
    float s = 0.f;
#pragma unroll 4
    for (int p = 0; p < P; p++) s += src[(size_t)p * ENC];
    splitbf(s * (1.f / 196.f), g_mean_h[idx], g_mean_l[idx]);
}

__global__ void split_hc() {
    int idx = blockIdx.x * 256 + threadIdx.x;
    int b = idx / DEC, d = idx % DEC;
    splitbf(g_hc[b * 2 * DEC + d], g_h_h[idx], g_h_l[idx]);
    g_c[idx] = g_hc[b * 2 * DEC + DEC + d];
}

// -------------------------- per-step kernels --------------------------------
// Fused embed + scores + softmax: one block per batch row.
__global__ void __launch_bounds__(256)
scores_softmax_kernel(const float* __restrict__ emb,
                      const int* __restrict__ cap,
                      const float* __restrict__ w_att,
                      const float* __restrict__ b_att, int t) {
    __shared__ float s_dec[ATT];
    __shared__ float s_w[ATT];
    __shared__ float s_sc[P];
    __shared__ float red[256];
    int b = blockIdx.x, tid = threadIdx.x;
    int warp = tid >> 5, lane = tid & 31;

    if (tid < 128) {       // embed copy -> x[b, 0:EMB] planes
        int cidx = cap[b * T + t];
        float4 v = reinterpret_cast<const float4*>(
            emb + (size_t)cidx * EMB)[tid];
        int o = b * XDIM + tid * 4;
        splitbf(v.x, g_x_h[o + 0], g_x_l[o + 0]);
        splitbf(v.y, g_x_h[o + 1], g_x_l[o + 1]);
        splitbf(v.z, g_x_h[o + 2], g_x_l[o + 2]);
        splitbf(v.w, g_x_h[o + 3], g_x_l[o + 3]);
    }
    for (int i = tid; i < ATT; i += 256) {
        s_dec[i] = g_hall[b * HALLN + i];
        s_w[i]   = w_att[i];
    }
    __syncthreads();
    float batt = b_att[0];
    for (int p = warp; p < P; p += 8) {
        const float* ep = &g_encproj[((size_t)(b * P + p)) * ATT];
        float s = 0.f;
#pragma unroll 4
        for (int a = lane; a < ATT; a += 32) {
            float e = ep[a] + s_dec[a];
            s += fmaxf(e, 0.f) * s_w[a];
        }
#pragma unroll
        for (int o = 16; o; o >>= 1) s += __shfl_down_sync(0xffffffffu, s, o);
        if (lane == 0) s_sc[p] = s + batt;
    }
    __syncthreads();
    float v = (tid < P) ? s_sc[tid] : -1e30f;
    red[tid] = v;
    __syncthreads();
    for (int o = 128; o; o >>= 1) {
        if (tid < o) red[tid] = fmaxf(red[tid], red[tid + o]);
        __syncthreads();
    }
    float m = red[0];
    __syncthreads();
    float e = (tid < P) ? expf(v - m) : 0.f;
    red[tid] = e;
    __syncthreads();
    for (int o = 128; o; o >>= 1) {
        if (tid < o) red[tid] += red[tid + o];
        __syncthreads();
    }
    if (tid < P) g_alpha[b * P + tid] = e / red[0];
}

// x[b, EMB+ch] = sigmoid(fbeta) * sum_p alpha[b,p]*enc_out[b,p,ch]
__global__ void context_kernel(const float* __restrict__ enc_out) {
    __shared__ float s_a[P];
    int b = blockIdx.x, tid = threadIdx.x;
    int ch = blockIdx.y * 256 + tid;
    if (tid < P) s_a[tid] = g_alpha[b * P + tid];
    __syncthreads();
    const float* eb = enc_out + (size_t)b * P * ENC + ch;
    float acc = 0.f;
#pragma unroll 4
    for (int p = 0; p < P; p++) acc = fmaf(s_a[p], eb[(size_t)p * ENC], acc);
    float gate = 1.f / (1.f + expf(-g_hall[b * HALLN + ATT + ch]));
    int o = b * XDIM + EMB + ch;
    splitbf(gate * acc, g_x_h[o], g_x_l[o]);
}

// Deterministic split-K reduce + LSTM cell; writes h planes + c.
__global__ void lstm_kernel() {
    int idx = blockIdx.x * 256 + threadIdx.x;
    int b = idx / DEC, d = idx % DEC;
    const float* hallg = &g_hall[b * HALLN + ATT + ENC];
    float gi = hallg[d];
    float gf = hallg[DEC + d];
    float gg = hallg[2 * DEC + d];
    float go = hallg[3 * DEC + d];
#pragma unroll
    for (int s = 0; s < KSPLIT; s++) {
        const float* pp = &g_gpart[((size_t)s * B + b) * G4];
        gi += pp[d];
        gf += pp[DEC + d];
        gg += pp[2 * DEC + d];
        go += pp[3 * DEC + d];
    }
    float c  = g_c[idx];
    float si = 1.f / (1.f + expf(-gi));
    float sf = 1.f / (1.f + expf(-gf));
    float so = 1.f / (1.f + expf(-go));
    float cn = sf * c + si * tanhf(gg);
    float hn = so * tanhf(cn);
    g_c[idx] = cn;
    splitbf(hn, g_h_h[idx], g_h_l[idx]);
}

// ------------------------------- launcher -----------------------------------
extern "C" void kernel_launch(void* const* d_in, const int* in_sizes, int n_in,
                              void* d_out, int out_size) {
    const float* enc_out   = (const float*)d_in[0];
    const int*   captions  = (const int*)  d_in[1];
    const float* emb       = (const float*)d_in[2];
    const float* W_init_h  = (const float*)d_in[3];
    const float* b_init_h  = (const float*)d_in[4];
    const float* W_init_c  = (const float*)d_in[5];
    const float* b_init_c  = (const float*)d_in[6];
    const float* W_enc_att = (const float*)d_in[7];
    const float* b_enc_att = (const float*)d_in[8];
    const float* W_dec_att = (const float*)d_in[9];
    const float* b_dec_att = (const float*)d_in[10];
    const float* w_att     = (const float*)d_in[11];
    const float* b_att     = (const float*)d_in[12];
    const float* W_fbeta   = (const float*)d_in[13];
    const float* b_fbeta   = (const float*)d_in[14];
    const float* W_ih      = (const float*)d_in[15];
    const float* b_ih      = (const float*)d_in[16];
    const float* W_hh      = (const float*)d_in[17];
    const float* b_hh      = (const float*)d_in[18];
    const float* W_fc      = (const float*)d_in[19];
    const float* b_fc      = (const float*)d_in[20];
    float* out = (float*)d_out;

    bf16 *pMh, *pMl, *pHh, *pHl, *pXh, *pXl, *pEh, *pEl;
    bf16 *pWencH, *pWencL, *pWinH, *pWinL, *pWcH, *pWcL, *pWihH, *pWihL;
    float *p_hc, *p_encproj, *p_hall, *p_gpart, *p_ball, *p_binit;
    cudaGetSymbolAddress((void**)&pEh, g_E_h);
    cudaGetSymbolAddress((void**)&pEl, g_E_l);
    cudaGetSymbolAddress((void**)&pMh, g_mean_h);
    cudaGetSymbolAddress((void**)&pMl, g_mean_l);
    cudaGetSymbolAddress((void**)&pHh, g_h_h);
    cudaGetSymbolAddress((void**)&pHl, g_h_l);
    cudaGetSymbolAddress((void**)&pXh, g_x_h);
    cudaGetSymbolAddress((void**)&pXl, g_x_l);
    cudaGetSymbolAddress((void**)&pWencH, g_WencT_h);
    cudaGetSymbolAddress((void**)&pWencL, g_WencT_l);
    cudaGetSymbolAddress((void**)&pWinH, g_WinitT_h);
    cudaGetSymbolAddress((void**)&pWinL, g_WinitT_l);
    cudaGetSymbolAddress((void**)&pWcH, g_WcombT_h);
    cudaGetSymbolAddress((void**)&pWcL, g_WcombT_l);
    cudaGetSymbolAddress((void**)&pWihH, g_WihT_h);
    cudaGetSymbolAddress((void**)&pWihL, g_WihT_l);
    cudaGetSymbolAddress((void**)&p_hc, g_hc);
    cudaGetSymbolAddress((void**)&p_encproj, g_encproj);
    cudaGetSymbolAddress((void**)&p_hall, g_hall);
    cudaGetSymbolAddress((void**)&p_gpart, g_gpart);
    cudaGetSymbolAddress((void**)&p_ball, g_ball);
    cudaGetSymbolAddress((void**)&p_binit, g_binit);

    cudaFuncSetAttribute(gemm_bf3,
                         cudaFuncAttributeMaxDynamicSharedMemorySize,
                         GEMM_SMEM);

    // ---- one-time precompute ----
    pack_weights<<<(STOT + 255) / 256, 256>>>(W_enc_att, W_init_h, W_init_c,
                                              W_dec_att, W_fbeta, W_hh, W_fc,
                                              W_ih);
    pack_bias<<<(HALLN + 2 * DEC + 255) / 256, 256>>>(b_dec_att, b_fbeta, b_hh,
                                                      b_ih, b_init_h, b_init_c);
    split_encout<<<(int)(((size_t)B * P * ENC / 4 + 255) / 256), 256>>>(enc_out);

    // enc_proj = enc_out @ W_enc_att + b  -> fp32 [25088, 512]
    gemm_bf3<<<dim3(ATT / 128, B * P / 128, 1), 256, GEMM_SMEM>>>(
        pEh, pEl, pWencH, pWencL, p_encproj, nullptr, B * P, ATT, ATT, ENC,
        ATT, 0, b_enc_att, nullptr, ENC);

    mean_kernel<<<B * ENC / 256, 256>>>(enc_out);

    // [h0|c0] = mean @ [W_init_h|W_init_c] + b
    gemm_bf3<<<dim3(2 * DEC / 128, 1, 1), 256, GEMM_SMEM>>>(
        pMh, pMl, pWinH, pWinL, p_hc, nullptr, B, 2 * DEC, 2 * DEC, ENC,
        2 * DEC, 0, p_binit, nullptr, ENC);
    split_hc<<<B * DEC / 256, 256>>>();

    // hall(0) = h0 @ Wall + ball  (first HALLN rows of comb weights)
    gemm_bf3<<<dim3(HALLN / 128, 1, 1), 256, GEMM_SMEM>>>(
        pHh, pHl, pWcH, pWcL, p_hall, nullptr, B, HALLN, HALLN, DEC, HALLN, 0,
        p_ball, nullptr, DEC);

    // ---- decode loop ----
    for (int t = 0; t < NSTEP; t++) {
        scores_softmax_kernel<<<B, 256>>>(emb, captions, w_att, b_att, t);
        context_kernel<<<dim3(B, ENC / 256), 256>>>(enc_out);

        // gates partials = x @ W_ih, split-K over XDIM (16 chunks, 256 CTAs)
        gemm_bf3<<<dim3(G4 / 128, 1, KSPLIT), 256, GEMM_SMEM>>>(
            pXh, pXl, pWihH, pWihL, p_gpart, nullptr, B, G4, G4, XDIM, G4, 0,
            nullptr, nullptr, KCHUNK);

        lstm_kernel<<<B * DEC / 256, 256>>>();

        // combined: [hall(t+1) | fc(t)] = h @ [Wall | Wfc]
        gemm_bf3<<<dim3((COMBN + 127) / 128, 1, 1), 256, GEMM_SMEM>>>(
            pHh, pHl, pWcH, pWcL, p_hall, out + (size_t)t * VOC, B, COMBN,
            HALLN, DEC, HALLN, NSTEP * VOC, p_ball, b_fc, DEC);
    }
}

// round 10
// speedup vs baseline: 1.3483x; 1.0748x over previous
#include <cuda_runtime.h>
#include <cuda_bf16.h>
#include <cstdint>
#include <cstddef>

// ---------------------------------------------------------------------------
// Show-Attend-Tell decoder. Round 10 = R7 (best passing) +
//  - coalesced smem-tiled weight transpose (one-time cost cut)
//  - BN=64 tile variant for the combined [hall|fc] step GEMM (229 CTAs)
// Context reads fp32 enc_out (exact; R9 lesson: no precision tricks on the
// recurrent path). Single stream, no static state.
// ---------------------------------------------------------------------------

constexpr int B    = 128;
constexpr int P    = 196;
constexpr int ENC  = 2048;
constexpr int EMB  = 512;
constexpr int DEC  = 512;
constexpr int ATT  = 512;
constexpr int VOC  = 10000;
constexpr int T    = 20;
constexpr int NSTEP = T - 1;           // 19
constexpr int G4   = 4 * DEC;          // 2048
constexpr int HALLN = ATT + ENC + G4;  // 4608
constexpr int COMBN = HALLN + VOC;     // 14608
constexpr int XDIM = EMB + ENC;        // 2560
constexpr int KSPLIT = 16;
constexpr int KCHUNK = XDIM / KSPLIT;  // 160

using bf16 = __nv_bfloat16;

// ----------------------------- device scratch ------------------------------
__device__ float g_hc[B * 2 * DEC];
__device__ float g_c[B * DEC];
__device__ __align__(16) bf16  g_h_h[B * DEC];
__device__ __align__(16) bf16  g_h_l[B * DEC];
__device__ __align__(16) bf16  g_mean_h[B * ENC];
__device__ __align__(16) bf16  g_mean_l[B * ENC];
__device__ __align__(16) bf16  g_x_h[B * XDIM];
__device__ __align__(16) bf16  g_x_l[B * XDIM];
__device__ __align__(16) bf16  g_E_h[(size_t)B * P * ENC];
__device__ __align__(16) bf16  g_E_l[(size_t)B * P * ENC];
__device__ float g_encproj[(size_t)B * P * ATT];
__device__ float g_hall[B * HALLN];
__device__ float g_alpha[B * P];
__device__ float g_gpart[(size_t)KSPLIT * B * G4];
// packed / transposed weights (bf16 hi/lo planes, [N][K] layout)
__device__ __align__(16) bf16 g_WencT_h[ATT * ENC];
__device__ __align__(16) bf16 g_WencT_l[ATT * ENC];
__device__ __align__(16) bf16 g_WinitT_h[2 * DEC * ENC];
__device__ __align__(16) bf16 g_WinitT_l[2 * DEC * ENC];
__device__ __align__(16) bf16 g_WcombT_h[COMBN * DEC];  // [Wall|Wfc]
__device__ __align__(16) bf16 g_WcombT_l[COMBN * DEC];
__device__ __align__(16) bf16 g_WihT_h[G4 * XDIM];
__device__ __align__(16) bf16 g_WihT_l[G4 * XDIM];
__device__ float g_ball[HALLN];
__device__ float g_binit[2 * DEC];

// ------------------------------ helpers -------------------------------------
__device__ __forceinline__ void splitbf(float x, bf16& h, bf16& l) {
    h = __float2bfloat16(x);
    l = __float2bfloat16(x - __bfloat162float(h));
}

__device__ __forceinline__ void mma_bf16(float c[4], const uint32_t a[4],
                                         const uint32_t b[2]) {
    asm volatile(
        "mma.sync.aligned.m16n8k16.row.col.f32.bf16.bf16.f32 "
        "{%0,%1,%2,%3}, {%4,%5,%6,%7}, {%8,%9}, {%0,%1,%2,%3};"
        : "+f"(c[0]), "+f"(c[1]), "+f"(c[2]), "+f"(c[3])
        : "r"(a[0]), "r"(a[1]), "r"(a[2]), "r"(a[3]), "r"(b[0]), "r"(b[1]));
}

__device__ __forceinline__ void ldsm4(uint32_t& r0, uint32_t& r1, uint32_t& r2,
                                      uint32_t& r3, uint32_t addr) {
    asm volatile(
        "ldmatrix.sync.aligned.m8n8.x4.shared.b16 {%0,%1,%2,%3}, [%4];"
        : "=r"(r0), "=r"(r1), "=r"(r2), "=r"(r3) : "r"(addr));
}

__device__ __forceinline__ void cpasync16(uint32_t dst, const void* src) {
    asm volatile("cp.async.cg.shared.global [%0], [%1], 16;"
                 :: "r"(dst), "l"(src));
}

// ------------------------------ 3xBF16 GEMM ---------------------------------
// C[M,N] = (Ah+Al)[M,K] @ (Bh+Bl)^T[N,K]. K-major bf16 operands, 3 passes.
// BM=128, BN=2*NT*8 (NT=8 -> 128, NT=4 -> 64). 256 thr, 8 warps (4Mx2N),
// warp tile 32x(NT*8). cp.async double buffer + ldmatrix.x4, PADK=20.
// Dual destination: cols < N1 -> C (ldc, bias); cols >= N1 -> C2 (ldc2, bias2).
// Split-K: z selects [z*kChunk,...), C += z*M*ldc (single-dest use only).
// Requires M%128==0, kChunk%32==0, K%8==0. N tail: B rows clamped, cols guarded.
constexpr int PADK = 20;

extern __shared__ uint32_t dynsm[];

template <int NT>
__global__ void __launch_bounds__(256, 2)
gemm_bf3(const bf16* __restrict__ Ah, const bf16* __restrict__ Al,
         const bf16* __restrict__ Bh, const bf16* __restrict__ Bl,
         float* __restrict__ C, float* __restrict__ C2,
         int M, int N, int N1, int K, int ldc, int ldc2,
         const float* __restrict__ bias, const float* __restrict__ bias2,
         int kChunk) {
    constexpr int BN     = 2 * NT * 8;
    constexpr int APLANE = 128 * PADK;     // u32
    constexpr int BPLANE = BN * PADK;      // u32
    constexpr int STAGE  = 2 * APLANE + 2 * BPLANE;
    constexpr int BLOADS = BN / 64;        // 16B tasks per thread for B

    const int tid  = threadIdx.x;
    const int warp = tid >> 5;
    const int lane = tid & 31;
    const int lr   = lane >> 2;
    const int lq   = lane & 3;
    const int wm   = warp & 3;
    const int wn   = warp >> 2;
    const int rowBase = blockIdx.y * 128;
    const int colBase = blockIdx.x * BN;
    const int k0 = blockIdx.z * kChunk;
    const int nIter = kChunk / 32;
    C += (size_t)blockIdx.z * M * ldc;

    const uint32_t smemBase = (uint32_t)__cvta_generic_to_shared(dynsm);

    auto load_stage = [&](int it, int stg) {
        const int kb = k0 + it * 32;
        const uint32_t sb = smemBase + (uint32_t)(stg * STAGE) * 4;
#pragma unroll
        for (int i = 0; i < 2; i++) {          // A: 128 rows x 4 chunks
            int idx = tid + i * 256;
            int r = idx >> 2, ch = idx & 3;
            const size_t off = (size_t)(rowBase + r) * K + kb + ch * 8;
            const uint32_t d = (uint32_t)(r * PADK + ch * 4) * 4;
            cpasync16(sb + d,              Ah + off);
            cpasync16(sb + APLANE * 4 + d, Al + off);
        }
#pragma unroll
        for (int i = 0; i < BLOADS; i++) {     // B: BN rows x 4 chunks
            int idx = tid + i * 256;
            int r = idx >> 2, ch = idx & 3;
            const int n = min(colBase + r, N - 1);
            const size_t off = (size_t)n * K + kb + ch * 8;
            const uint32_t d = (uint32_t)(r * PADK + ch * 4) * 4;
            cpasync16(sb + 2u * APLANE * 4 + d,            Bh + off);
            cpasync16(sb + (2u * APLANE + BPLANE) * 4 + d, Bl + off);
        }
    };

    const int aRow = (lane & 7) + ((lane >> 3) & 1) * 8;
    const int aK   = ((lane >> 4) & 1) * 4;
    const int bRow = (lane & 7) + ((lane >> 4) & 1) * 8;
    const int bK   = ((lane >> 3) & 1) * 4;

    float acc[2][NT][4];
#pragma unroll
    for (int mt = 0; mt < 2; mt++)
#pragma unroll
        for (int nt = 0; nt < NT; nt++)
#pragma unroll
            for (int j = 0; j < 4; j++) acc[mt][nt][j] = 0.f;

    load_stage(0, 0);
    asm volatile("cp.async.commit_group;");

    for (int it = 0; it < nIter; it++) {
        if (it + 1 < nIter) {
            load_stage(it + 1, (it + 1) & 1);
            asm volatile("cp.async.commit_group;");
            asm volatile("cp.async.wait_group 1;");
        } else {
            asm volatile("cp.async.wait_group 0;");
        }
        __syncthreads();

        const uint32_t sb = smemBase + (uint32_t)((it & 1) * STAGE) * 4;
#pragma unroll
        for (int s = 0; s < 2; s++) {
            const uint32_t ks = (uint32_t)(s * 8) * 4;
            uint32_t ah[2][4], al[2][4], bh[NT][2], bl[NT][2];
#pragma unroll
            for (int mt = 0; mt < 2; mt++) {
                uint32_t ra = (uint32_t)((wm * 32 + mt * 16 + aRow) * PADK +
                                         aK) * 4 + ks;
                ldsm4(ah[mt][0], ah[mt][1], ah[mt][2], ah[mt][3], sb + ra);
                ldsm4(al[mt][0], al[mt][1], al[mt][2], al[mt][3],
                      sb + APLANE * 4 + ra);
            }
#pragma unroll
            for (int np = 0; np < NT / 2; np++) {
                uint32_t rb = (uint32_t)((wn * NT * 8 + np * 16 + bRow) *
                                         PADK + bK) * 4 + ks;
                ldsm4(bh[2 * np][0], bh[2 * np][1], bh[2 * np + 1][0],
                      bh[2 * np + 1][1], sb + 2u * APLANE * 4 + rb);
                ldsm4(bl[2 * np][0], bl[2 * np][1], bl[2 * np + 1][0],
                      bl[2 * np + 1][1], sb + (2u * APLANE + BPLANE) * 4 + rb);
            }
#pragma unroll
            for (int nt = 0; nt < NT; nt++)
#pragma unroll
                for (int mt = 0; mt < 2; mt++) {
                    mma_bf16(acc[mt][nt], ah[mt], bh[nt]);
                    mma_bf16(acc[mt][nt], al[mt], bh[nt]);
                    mma_bf16(acc[mt][nt], ah[mt], bl[nt]);
                }
        }
        __syncthreads();
    }

#pragma unroll
    for (int mt = 0; mt < 2; mt++) {
        int r0 = rowBase + wm * 32 + mt * 16 + lr;
#pragma unroll
        for (int nt = 0; nt < NT; nt++) {
            int cbase = colBase + wn * NT * 8 + nt * 8 + 2 * lq;
#pragma unroll
            for (int cc = 0; cc < 2; cc++) {
                int c = cbase + cc;
                if (c >= N) continue;
                float v0 = acc[mt][nt][cc];
                float v1 = acc[mt][nt][2 + cc];
                if (c < N1) {
                    float bb = bias ? bias[c] : 0.f;
                    C[(size_t)r0 * ldc + c] = v0 + bb;
                    C[(size_t)(r0 + 8) * ldc + c] = v1 + bb;
                } else {
                    int c2 = c - N1;
                    float bb = bias2 ? bias2[c2] : 0.f;
                    C2[(size_t)r0 * ldc2 + c2] = v0 + bb;
                    C2[(size_t)(r0 + 8) * ldc2 + c2] = v1 + bb;
                }
            }
        }
    }
}

constexpr int SMEM_N8 = 2 * (2 * 128 * PADK + 2 * 128 * PADK) * 4;  // 81920
constexpr int SMEM_N4 = 2 * (2 * 128 * PADK + 2 * 64  * PADK) * 4;  // 61440

// ---------------------- coalesced transpose + split --------------------------
// dst[n*Krows + k] planes <- src[k*Ncols + n].  Krows % 32 == 0; N guarded.
__global__ void transpose_split(const float* __restrict__ src,
                                bf16* __restrict__ dh, bf16* __restrict__ dl,
                                int Krows, int Ncols) {
    __shared__ float tile[32][33];
    const int nb = blockIdx.x * 32, kb = blockIdx.y * 32;
    const int tx = threadIdx.x, ty = threadIdx.y;   // (32, 8)
#pragma unroll
    for (int j = 0; j < 4; j++) {
        int k = kb + ty + j * 8;
        int n = nb + tx;
        tile[ty + j * 8][tx] = (n < Ncols) ? src[(size_t)k * Ncols + n] : 0.f;
    }
    __syncthreads();
#pragma unroll
    for (int j = 0; j < 4; j++) {
        int n = nb + ty + j * 8;
        int k = kb + tx;
        if (n < Ncols) {
            bf16 h, l;
            splitbf(tile[tx][ty + j * 8], h, l);
            dh[(size_t)n * Krows + k] = h;
            dl[(size_t)n * Krows + k] = l;
        }
    }
}

// ---------------------------- other pack kernels ----------------------------
__global__ void pack_bias(const float* __restrict__ bd,
                          const float* __restrict__ bf,
                          const float* __restrict__ bhh,
                          const float* __restrict__ bih,
                          const float* __restrict__ bh0,
                          const float* __restrict__ bc0) {
    int c = blockIdx.x * 256 + threadIdx.x;
    if (c < HALLN) {
        float v;
        if (c < ATT)            v = bd[c];
        else if (c < ATT + ENC) v = bf[c - ATT];
        else                    v = bhh[c - ATT - ENC] + bih[c - ATT - ENC];
        g_ball[c] = v;
    } else if (c < HALLN + 2 * DEC) {
        int q = c - HALLN;
        g_binit[q] = (q < DEC) ? bh0[q] : bc0[q - DEC];
    }
}

__global__ void split_encout(const float* __restrict__ enc_out) {
    size_t i = (size_t)blockIdx.x * 256 + threadIdx.x;
    float4 v = reinterpret_cast<const float4*>(enc_out)[i];
    bf16 h0, l0, h1, l1, h2, l2, h3, l3;
    splitbf(v.x, h0, l0); splitbf(v.y, h1, l1);
    splitbf(v.z, h2, l2); splitbf(v.w, h3, l3);
    __nv_bfloat162* Eh2 = reinterpret_cast<__nv_bfloat162*>(g_E_h);
    __nv_bfloat162* El2 = reinterpret_cast<__nv_bfloat162*>(g_E_l);
    Eh2[i * 2 + 0] = __nv_bfloat162(h0, h1);
    Eh2[i * 2 + 1] = __nv_bfloat162(h2, h3);
    El2[i * 2 + 0] = __nv_bfloat162(l0, l1);
    El2[i * 2 + 1] = __nv_bfloat162(l2, l3);
}

__global__ void mean_kernel(const float* __restrict__ enc_out) {
    int idx = blockIdx.x * 256 + threadIdx.x;
    int b = idx / ENC, e = idx % ENC;
    const float* src = enc_out + (size_t)b * P * ENC + e;
    float s = 0.f;
#pragma unroll 4
    for (int p = 0; p < P; p++) s += src[(size_t)p * ENC];
    splitbf(s * (1.f / 196.f), g_mean_h[idx], g_mean_l[idx]);
}

__global__ void split_hc() {
    int idx = blockIdx.x * 256 + threadIdx.x;
    int b = idx / DEC, d = idx % DEC;
    splitbf(g_hc[b * 2 * DEC + d], g_h_h[idx], g_h_l[idx]);
    g_c[idx] = g_hc[b * 2 * DEC + DEC + d];
}

// -------------------------- per-step kernels --------------------------------
// Fused embed + scores + softmax: one block per batch row.
__global__ void __launch_bounds__(256)
scores_softmax_kernel(const float* __restrict__ emb,
                      const int* __restrict__ cap,
                      const float* __restrict__ w_att,
                      const float* __restrict__ b_att, int t) {
    __shared__ float s_dec[ATT];
    __shared__ float s_w[ATT];
    __shared__ float s_sc[P];
    __shared__ float red[256];
    int b = blockIdx.x, tid = threadIdx.x;
    int warp = tid >> 5, lane = tid & 31;

    if (tid < 128) {       // embed copy -> x[b, 0:EMB] planes
        int cidx = cap[b * T + t];
        float4 v = reinterpret_cast<const float4*>(
            emb + (size_t)cidx * EMB)[tid];
        int o = b * XDIM + tid * 4;
        splitbf(v.x, g_x_h[o + 0], g_x_l[o + 0]);
        splitbf(v.y, g_x_h[o + 1], g_x_l[o + 1]);
        splitbf(v.z, g_x_h[o + 2], g_x_l[o + 2]);
        splitbf(v.w, g_x_h[o + 3], g_x_l[o + 3]);
    }
    for (int i = tid; i < ATT; i += 256) {
        s_dec[i] = g_hall[b * HALLN + i];
        s_w[i]   = w_att[i];
    }
    __syncthreads();
    float batt = b_att[0];
    for (int p = warp; p < P; p += 8) {
        const float* ep = &g_encproj[((size_t)(b * P + p)) * ATT];
        float s = 0.f;
#pragma unroll 4
        for (int a = lane; a < ATT; a += 32) {
            float e = ep[a] + s_dec[a];
            s += fmaxf(e, 0.f) * s_w[a];
        }
#pragma unroll
        for (int o = 16; o; o >>= 1) s += __shfl_down_sync(0xffffffffu, s, o);
        if (lane == 0) s_sc[p] = s + batt;
    }
    __syncthreads();
    float v = (tid < P) ? s_sc[tid] : -1e30f;
    red[tid] = v;
    __syncthreads();
    for (int o = 128; o; o >>= 1) {
        if (tid < o) red[tid] = fmaxf(red[tid], red[tid + o]);
        __syncthreads();
    }
    float m = red[0];
    __syncthreads();
    float e = (tid < P) ? expf(v - m) : 0.f;
    red[tid] = e;
    __syncthreads();
    for (int o = 128; o; o >>= 1) {
        if (tid < o) red[tid] += red[tid + o];
        __syncthreads();
    }
    if (tid < P) g_alpha[b * P + tid] = e / red[0];
}

// x[b, EMB+ch] = sigmoid(fbeta) * sum_p alpha[b,p]*enc_out[b,p,ch]  (fp32)
__global__ void context_kernel(const float* __restrict__ enc_out) {
    __shared__ float s_a[P];
    int b = blockIdx.x, tid = threadIdx.x;
    int ch = blockIdx.y * 256 + tid;
    if (tid < P) s_a[tid] = g_alpha[b * P + tid];
    __syncthreads();
    const float* eb = enc_out + (size_t)b * P * ENC + ch;
    float acc = 0.f;
#pragma unroll 4
    for (int p = 0; p < P; p++) acc = fmaf(s_a[p], eb[(size_t)p * ENC], acc);
    float gate = 1.f / (1.f + expf(-g_hall[b * HALLN + ATT + ch]));
    int o = b * XDIM + EMB + ch;
    splitbf(gate * acc, g_x_h[o], g_x_l[o]);
}

// Deterministic split-K reduce + LSTM cell; writes h planes + c.
__global__ void lstm_kernel() {
    int idx = blockIdx.x * 256 + threadIdx.x;
    int b = idx / DEC, d = idx % DEC;
    const float* hallg = &g_hall[b * HALLN + ATT + ENC];
    float gi = hallg[d];
    float gf = hallg[DEC + d];
    float gg = hallg[2 * DEC + d];
    float go = hallg[3 * DEC + d];
#pragma unroll
    for (int s = 0; s < KSPLIT; s++) {
        const float* pp = &g_gpart[((size_t)s * B + b) * G4];
        gi += pp[d];
        gf += pp[DEC + d];
        gg += pp[2 * DEC + d];
        go += pp[3 * DEC + d];
    }
    float c  = g_c[idx];
    float si = 1.f / (1.f + expf(-gi));
    float sf = 1.f / (1.f + expf(-gf));
    float so = 1.f / (1.f + expf(-go));
    float cn = sf * c + si * tanhf(gg);
    float hn = so * tanhf(cn);
    g_c[idx] = cn;
    splitbf(hn, g_h_h[idx], g_h_l[idx]);
}

// ------------------------------- launcher -----------------------------------
extern "C" void kernel_launch(void* const* d_in, const int* in_sizes, int n_in,
                              void* d_out, int out_size) {
    const float* enc_out   = (const float*)d_in[0];
    const int*   captions  = (const int*)  d_in[1];
    const float* emb       = (const float*)d_in[2];
    const float* W_init_h  = (const float*)d_in[3];
    const float* b_init_h  = (const float*)d_in[4];
    const float* W_init_c  = (const float*)d_in[5];
    const float* b_init_c  = (const float*)d_in[6];
    const float* W_enc_att = (const float*)d_in[7];
    const float* b_enc_att = (const float*)d_in[8];
    const float* W_dec_att = (const float*)d_in[9];
    const float* b_dec_att = (const float*)d_in[10];
    const float* w_att     = (const float*)d_in[11];
    const float* b_att     = (const float*)d_in[12];
    const float* W_fbeta   = (const float*)d_in[13];
    const float* b_fbeta   = (const float*)d_in[14];
    const float* W_ih      = (const float*)d_in[15];
    const float* b_ih      = (const float*)d_in[16];
    const float* W_hh      = (const float*)d_in[17];
    const float* b_hh      = (const float*)d_in[18];
    const float* W_fc      = (const float*)d_in[19];
    const float* b_fc      = (const float*)d_in[20];
    float* out = (float*)d_out;

    bf16 *pMh, *pMl, *pHh, *pHl, *pXh, *pXl, *pEh, *pEl;
    bf16 *pWencH, *pWencL, *pWinH, *pWinL, *pWcH, *pWcL, *pWihH, *pWihL;
    float *p_hc, *p_encproj, *p_hall, *p_gpart, *p_ball, *p_binit;
    cudaGetSymbolAddress((void**)&pEh, g_E_h);
    cudaGetSymbolAddress((void**)&pEl, g_E_l);
    cudaGetSymbolAddress((void**)&pMh, g_mean_h);
    cudaGetSymbolAddress((void**)&pMl, g_mean_l);
    cudaGetSymbolAddress((void**)&pHh, g_h_h);
    cudaGetSymbolAddress((void**)&pHl, g_h_l);
    cudaGetSymbolAddress((void**)&pXh, g_x_h);
    cudaGetSymbolAddress((void**)&pXl, g_x_l);
    cudaGetSymbolAddress((void**)&pWencH, g_WencT_h);
    cudaGetSymbolAddress((void**)&pWencL, g_WencT_l);
    cudaGetSymbolAddress((void**)&pWinH, g_WinitT_h);
    cudaGetSymbolAddress((void**)&pWinL, g_WinitT_l);
    cudaGetSymbolAddress((void**)&pWcH, g_WcombT_h);
    cudaGetSymbolAddress((void**)&pWcL, g_WcombT_l);
    cudaGetSymbolAddress((void**)&pWihH, g_WihT_h);
    cudaGetSymbolAddress((void**)&pWihL, g_WihT_l);
    cudaGetSymbolAddress((void**)&p_hc, g_hc);
    cudaGetSymbolAddress((void**)&p_encproj, g_encproj);
    cudaGetSymbolAddress((void**)&p_hall, g_hall);
    cudaGetSymbolAddress((void**)&p_gpart, g_gpart);
    cudaGetSymbolAddress((void**)&p_ball, g_ball);
    cudaGetSymbolAddress((void**)&p_binit, g_binit);

    cudaFuncSetAttribute(gemm_bf3<8>,
                         cudaFuncAttributeMaxDynamicSharedMemorySize, SMEM_N8);
    cudaFuncSetAttribute(gemm_bf3<4>,
                         cudaFuncAttributeMaxDynamicSharedMemorySize, SMEM_N4);

    // ---- one-time precompute: coalesced transposes ----
    dim3 tb(32, 8);
    transpose_split<<<dim3(ATT / 32, ENC / 32), tb>>>(      // W_enc_att
        W_enc_att, pWencH, pWencL, ENC, ATT);
    transpose_split<<<dim3(DEC / 32, ENC / 32), tb>>>(      // W_init_h
        W_init_h, pWinH, pWinL, ENC, DEC);
    transpose_split<<<dim3(DEC / 32, ENC / 32), tb>>>(      // W_init_c
        W_init_c, pWinH + (size_t)DEC * ENC, pWinL + (size_t)DEC * ENC, ENC,
        DEC);
    transpose_split<<<dim3(ATT / 32, DEC / 32), tb>>>(      // W_dec_att
        W_dec_att, pWcH, pWcL, DEC, ATT);
    transpose_split<<<dim3(ENC / 32, DEC / 32), tb>>>(      // W_fbeta
        W_fbeta, pWcH + (size_t)ATT * DEC, pWcL + (size_t)ATT * DEC, DEC, ENC);
    transpose_split<<<dim3(G4 / 32, DEC / 32), tb>>>(       // W_hh
        W_hh, pWcH + (size_t)(ATT + ENC) * DEC, pWcL + (size_t)(ATT + ENC) * DEC,
        DEC, G4);
    transpose_split<<<dim3((VOC + 31) / 32, DEC / 32), tb>>>(  // W_fc
        W_fc, pWcH + (size_t)HALLN * DEC, pWcL + (size_t)HALLN * DEC, DEC, VOC);
    transpose_split<<<dim3(G4 / 32, XDIM / 32), tb>>>(      // W_ih
        W_ih, pWihH, pWihL, XDIM, G4);

    pack_bias<<<(HALLN + 2 * DEC + 255) / 256, 256>>>(b_dec_att, b_fbeta, b_hh,
                                                      b_ih, b_init_h, b_init_c);
    split_encout<<<(int)(((size_t)B * P * ENC / 4 + 255) / 256), 256>>>(enc_out);

    // enc_proj = enc_out @ W_enc_att + b  -> fp32 [25088, 512]
    gemm_bf3<8><<<dim3(ATT / 128, B * P / 128, 1), 256, SMEM_N8>>>(
        pEh, pEl, pWencH, pWencL, p_encproj, nullptr, B * P, ATT, ATT, ENC,
        ATT, 0, b_enc_att, nullptr, ENC);

    mean_kernel<<<B * ENC / 256, 256>>>(enc_out);

    // [h0|c0] = mean @ [W_init_h|W_init_c] + b
    gemm_bf3<8><<<dim3(2 * DEC / 128, 1, 1), 256, SMEM_N8>>>(
        pMh, pMl, pWinH, pWinL, p_hc, nullptr, B, 2 * DEC, 2 * DEC, ENC,
        2 * DEC, 0, p_binit, nullptr, ENC);
    split_hc<<<B * DEC / 256, 256>>>();

    // hall(0) = h0 @ Wall + ball
    gemm_bf3<8><<<dim3(HALLN / 128, 1, 1), 256, SMEM_N8>>>(
        pHh, pHl, pWcH, pWcL, p_hall, nullptr, B, HALLN, HALLN, DEC, HALLN, 0,
        p_ball, nullptr, DEC);

    // ---- decode loop ----
    for (int t = 0; t < NSTEP; t++) {
        scores_softmax_kernel<<<B, 256>>>(emb, captions, w_att, b_att, t);
        context_kernel<<<dim3(B, ENC / 256), 256>>>(enc_out);

        // gates partials = x @ W_ih, split-K over XDIM (16 chunks, 256 CTAs)
        gemm_bf3<8><<<dim3(G4 / 128, 1, KSPLIT), 256, SMEM_N8>>>(
            pXh, pXl, pWihH, pWihL, p_gpart, nullptr, B, G4, G4, XDIM, G4, 0,
            nullptr, nullptr, KCHUNK);

        lstm_kernel<<<B * DEC / 256, 256>>>();

        // combined: [hall(t+1) | fc(t)] = h @ [Wall | Wfc], BN=64 -> 229 CTAs
        gemm_bf3<4><<<dim3((COMBN + 63) / 64, 1, 1), 256, SMEM_N4>>>(
            pHh, pHl, pWcH, pWcL, p_hall, out + (size_t)t * VOC, B, COMBN,
            HALLN, DEC, HALLN, NSTEP * VOC, p_ball, b_fc, DEC);
    }
}

// round 11
// speedup vs baseline: 1.3911x; 1.0318x over previous
#include <cuda_runtime.h>
#include <cuda_bf16.h>
#include <cuda_fp16.h>
#include <cstdint>
#include <cstddef>

// ---------------------------------------------------------------------------
// Show-Attend-Tell decoder. Round 11 = R10 + fp16-hi context plane:
// split_encout additionally writes g_E16 (fp16, 102 MB) which ONLY the
// context kernel reads (halves the dominant per-step stream). ε(fp16)=2^-11;
// R9-calibrated transfer (0.8x) predicts final rel_err ~3.9e-4 < 1e-3.
// All GEMMs keep the exact-class bf16 3-pass path.
// ---------------------------------------------------------------------------

constexpr int B    = 128;
constexpr int P    = 196;
constexpr int ENC  = 2048;
constexpr int EMB  = 512;
constexpr int DEC  = 512;
constexpr int ATT  = 512;
constexpr int VOC  = 10000;
constexpr int T    = 20;
constexpr int NSTEP = T - 1;           // 19
constexpr int G4   = 4 * DEC;          // 2048
constexpr int HALLN = ATT + ENC + G4;  // 4608
constexpr int COMBN = HALLN + VOC;     // 14608
constexpr int XDIM = EMB + ENC;        // 2560
constexpr int KSPLIT = 16;
constexpr int KCHUNK = XDIM / KSPLIT;  // 160

using bf16 = __nv_bfloat16;

// ----------------------------- device scratch ------------------------------
__device__ float g_hc[B * 2 * DEC];
__device__ float g_c[B * DEC];
__device__ __align__(16) bf16  g_h_h[B * DEC];
__device__ __align__(16) bf16  g_h_l[B * DEC];
__device__ __align__(16) bf16  g_mean_h[B * ENC];
__device__ __align__(16) bf16  g_mean_l[B * ENC];
__device__ __align__(16) bf16  g_x_h[B * XDIM];
__device__ __align__(16) bf16  g_x_l[B * XDIM];
__device__ __align__(16) bf16  g_E_h[(size_t)B * P * ENC];
__device__ __align__(16) bf16  g_E_l[(size_t)B * P * ENC];
__device__ __align__(16) __half g_E16[(size_t)B * P * ENC];  // context-only
__device__ float g_encproj[(size_t)B * P * ATT];
__device__ float g_hall[B * HALLN];
__device__ float g_alpha[B * P];
__device__ float g_gpart[(size_t)KSPLIT * B * G4];
// packed / transposed weights (bf16 hi/lo planes, [N][K] layout)
__device__ __align__(16) bf16 g_WencT_h[ATT * ENC];
__device__ __align__(16) bf16 g_WencT_l[ATT * ENC];
__device__ __align__(16) bf16 g_WinitT_h[2 * DEC * ENC];
__device__ __align__(16) bf16 g_WinitT_l[2 * DEC * ENC];
__device__ __align__(16) bf16 g_WcombT_h[COMBN * DEC];  // [Wall|Wfc]
__device__ __align__(16) bf16 g_WcombT_l[COMBN * DEC];
__device__ __align__(16) bf16 g_WihT_h[G4 * XDIM];
__device__ __align__(16) bf16 g_WihT_l[G4 * XDIM];
__device__ float g_ball[HALLN];
__device__ float g_binit[2 * DEC];

// ------------------------------ helpers -------------------------------------
__device__ __forceinline__ void splitbf(float x, bf16& h, bf16& l) {
    h = __float2bfloat16(x);
    l = __float2bfloat16(x - __bfloat162float(h));
}

__device__ __forceinline__ void mma_bf16(float c[4], const uint32_t a[4],
                                         const uint32_t b[2]) {
    asm volatile(
        "mma.sync.aligned.m16n8k16.row.col.f32.bf16.bf16.f32 "
        "{%0,%1,%2,%3}, {%4,%5,%6,%7}, {%8,%9}, {%0,%1,%2,%3};"
        : "+f"(c[0]), "+f"(c[1]), "+f"(c[2]), "+f"(c[3])
        : "r"(a[0]), "r"(a[1]), "r"(a[2]), "r"(a[3]), "r"(b[0]), "r"(b[1]));
}

__device__ __forceinline__ void ldsm4(uint32_t& r0, uint32_t& r1, uint32_t& r2,
                                      uint32_t& r3, uint32_t addr) {
    asm volatile(
        "ldmatrix.sync.aligned.m8n8.x4.shared.b16 {%0,%1,%2,%3}, [%4];"
        : "=r"(r0), "=r"(r1), "=r"(r2), "=r"(r3) : "r"(addr));
}

__device__ __forceinline__ void cpasync16(uint32_t dst, const void* src) {
    asm volatile("cp.async.cg.shared.global [%0], [%1], 16;"
                 :: "r"(dst), "l"(src));
}

// ------------------------------ 3xBF16 GEMM ---------------------------------
// C[M,N] = (Ah+Al)[M,K] @ (Bh+Bl)^T[N,K]. K-major bf16 operands, 3 passes.
// BM=128, BN=2*NT*8 (NT=8 -> 128, NT=4 -> 64). 256 thr, 8 warps (4Mx2N),
// warp tile 32x(NT*8). cp.async double buffer + ldmatrix.x4, PADK=20.
// Dual destination: cols < N1 -> C (ldc, bias); cols >= N1 -> C2 (ldc2, bias2).
// Split-K: z selects [z*kChunk,...), C += z*M*ldc (single-dest use only).
// Requires M%128==0, kChunk%32==0, K%8==0. N tail: B rows clamped, cols guarded.
constexpr int PADK = 20;

extern __shared__ uint32_t dynsm[];

template <int NT>
__global__ void __launch_bounds__(256, 2)
gemm_bf3(const bf16* __restrict__ Ah, const bf16* __restrict__ Al,
         const bf16* __restrict__ Bh, const bf16* __restrict__ Bl,
         float* __restrict__ C, float* __restrict__ C2,
         int M, int N, int N1, int K, int ldc, int ldc2,
         const float* __restrict__ bias, const float* __restrict__ bias2,
         int kChunk) {
    constexpr int BN     = 2 * NT * 8;
    constexpr int APLANE = 128 * PADK;     // u32
    constexpr int BPLANE = BN * PADK;      // u32
    constexpr int STAGE  = 2 * APLANE + 2 * BPLANE;
    constexpr int BLOADS = BN / 64;        // 16B tasks per thread for B

    const int tid  = threadIdx.x;
    const int warp = tid >> 5;
    const int lane = tid & 31;
    const int lr   = lane >> 2;
    const int lq   = lane & 3;
    const int wm   = warp & 3;
    const int wn   = warp >> 2;
    const int rowBase = blockIdx.y * 128;
    const int colBase = blockIdx.x * BN;
    const int k0 = blockIdx.z * kChunk;
    const int nIter = kChunk / 32;
    C += (size_t)blockIdx.z * M * ldc;

    const uint32_t smemBase = (uint32_t)__cvta_generic_to_shared(dynsm);

    auto load_stage = [&](int it, int stg) {
        const int kb = k0 + it * 32;
        const uint32_t sb = smemBase + (uint32_t)(stg * STAGE) * 4;
#pragma unroll
        for (int i = 0; i < 2; i++) {          // A: 128 rows x 4 chunks
            int idx = tid + i * 256;
            int r = idx >> 2, ch = idx & 3;
            const size_t off = (size_t)(rowBase + r) * K + kb + ch * 8;
            const uint32_t d = (uint32_t)(r * PADK + ch * 4) * 4;
            cpasync16(sb + d,              Ah + off);
            cpasync16(sb + APLANE * 4 + d, Al + off);
        }
#pragma unroll
        for (int i = 0; i < BLOADS; i++) {     // B: BN rows x 4 chunks
            int idx = tid + i * 256;
            int r = idx >> 2, ch = idx & 3;
            const int n = min(colBase + r, N - 1);
            const size_t off = (size_t)n * K + kb + ch * 8;
            const uint32_t d = (uint32_t)(r * PADK + ch * 4) * 4;
            cpasync16(sb + 2u * APLANE * 4 + d,            Bh + off);
            cpasync16(sb + (2u * APLANE + BPLANE) * 4 + d, Bl + off);
        }
    };

    const int aRow = (lane & 7) + ((lane >> 3) & 1) * 8;
    const int aK   = ((lane >> 4) & 1) * 4;
    const int bRow = (lane & 7) + ((lane >> 4) & 1) * 8;
    const int bK   = ((lane >> 3) & 1) * 4;

    float acc[2][NT][4];
#pragma unroll
    for (int mt = 0; mt < 2; mt++)
#pragma unroll
        for (int nt = 0; nt < NT; nt++)
#pragma unroll
            for (int j = 0; j < 4; j++) acc[mt][nt][j] = 0.f;

    load_stage(0, 0);
    asm volatile("cp.async.commit_group;");

    for (int it = 0; it < nIter; it++) {
        if (it + 1 < nIter) {
            load_stage(it + 1, (it + 1) & 1);
            asm volatile("cp.async.commit_group;");
            asm volatile("cp.async.wait_group 1;");
        } else {
            asm volatile("cp.async.wait_group 0;");
        }
        __syncthreads();

        const uint32_t sb = smemBase + (uint32_t)((it & 1) * STAGE) * 4;
#pragma unroll
        for (int s = 0; s < 2; s++) {
            const uint32_t ks = (uint32_t)(s * 8) * 4;
            uint32_t ah[2][4], al[2][4], bh[NT][2], bl[NT][2];
#pragma unroll
            for (int mt = 0; mt < 2; mt++) {
                uint32_t ra = (uint32_t)((wm * 32 + mt * 16 + aRow) * PADK +
                                         aK) * 4 + ks;
                ldsm4(ah[mt][0], ah[mt][1], ah[mt][2], ah[mt][3], sb + ra);
                ldsm4(al[mt][0], al[mt][1], al[mt][2], al[mt][3],
                      sb + APLANE * 4 + ra);
            }
#pragma unroll
            for (int np = 0; np < NT / 2; np++) {
                uint32_t rb = (uint32_t)((wn * NT * 8 + np * 16 + bRow) *
                                         PADK + bK) * 4 + ks;
                ldsm4(bh[2 * np][0], bh[2 * np][1], bh[2 * np + 1][0],
                      bh[2 * np + 1][1], sb + 2u * APLANE * 4 + rb);
                ldsm4(bl[2 * np][0], bl[2 * np][1], bl[2 * np + 1][0],
                      bl[2 * np + 1][1], sb + (2u * APLANE + BPLANE) * 4 + rb);
            }
#pragma unroll
            for (int nt = 0; nt < NT; nt++)
#pragma unroll
                for (int mt = 0; mt < 2; mt++) {
                    mma_bf16(acc[mt][nt], ah[mt], bh[nt]);
                    mma_bf16(acc[mt][nt], al[mt], bh[nt]);
                    mma_bf16(acc[mt][nt], ah[mt], bl[nt]);
                }
        }
        __syncthreads();
    }

#pragma unroll
    for (int mt = 0; mt < 2; mt++) {
        int r0 = rowBase + wm * 32 + mt * 16 + lr;
#pragma unroll
        for (int nt = 0; nt < NT; nt++) {
            int cbase = colBase + wn * NT * 8 + nt * 8 + 2 * lq;
#pragma unroll
            for (int cc = 0; cc < 2; cc++) {
                int c = cbase + cc;
                if (c >= N) continue;
                float v0 = acc[mt][nt][cc];
                float v1 = acc[mt][nt][2 + cc];
                if (c < N1) {
                    float bb = bias ? bias[c] : 0.f;
                    C[(size_t)r0 * ldc + c] = v0 + bb;
                    C[(size_t)(r0 + 8) * ldc + c] = v1 + bb;
                } else {
                    int c2 = c - N1;
                    float bb = bias2 ? bias2[c2] : 0.f;
                    C2[(size_t)r0 * ldc2 + c2] = v0 + bb;
                    C2[(size_t)(r0 + 8) * ldc2 + c2] = v1 + bb;
                }
            }
        }
    }
}

constexpr int SMEM_N8 = 2 * (2 * 128 * PADK + 2 * 128 * PADK) * 4;  // 81920
constexpr int SMEM_N4 = 2 * (2 * 128 * PADK + 2 * 64  * PADK) * 4;  // 61440

// ---------------------- coalesced transpose + split --------------------------
// dst[n*Krows + k] planes <- src[k*Ncols + n].  Krows % 32 == 0; N guarded.
__global__ void transpose_split(const float* __restrict__ src,
                                bf16* __restrict__ dh, bf16* __restrict__ dl,
                                int Krows, int Ncols) {
    __shared__ float tile[32][33];
    const int nb = blockIdx.x * 32, kb = blockIdx.y * 32;
    const int tx = threadIdx.x, ty = threadIdx.y;   // (32, 8)
#pragma unroll
    for (int j = 0; j < 4; j++) {
        int k = kb + ty + j * 8;
        int n = nb + tx;
        tile[ty + j * 8][tx] = (n < Ncols) ? src[(size_t)k * Ncols + n] : 0.f;
    }
    __syncthreads();
#pragma unroll
    for (int j = 0; j < 4; j++) {
        int n = nb + ty + j * 8;
        int k = kb + tx;
        if (n < Ncols) {
            bf16 h, l;
            splitbf(tile[tx][ty + j * 8], h, l);
            dh[(size_t)n * Krows + k] = h;
            dl[(size_t)n * Krows + k] = l;
        }
    }
}

// ---------------------------- other pack kernels ----------------------------
__global__ void pack_bias(const float* __restrict__ bd,
                          const float* __restrict__ bf,
                          const float* __restrict__ bhh,
                          const float* __restrict__ bih,
                          const float* __restrict__ bh0,
                          const float* __restrict__ bc0) {
    int c = blockIdx.x * 256 + threadIdx.x;
    if (c < HALLN) {
        float v;
        if (c < ATT)            v = bd[c];
        else if (c < ATT + ENC) v = bf[c - ATT];
        else                    v = bhh[c - ATT - ENC] + bih[c - ATT - ENC];
        g_ball[c] = v;
    } else if (c < HALLN + 2 * DEC) {
        int q = c - HALLN;
        g_binit[q] = (q < DEC) ? bh0[q] : bc0[q - DEC];
    }
}

__global__ void split_encout(const float* __restrict__ enc_out) {
    size_t i = (size_t)blockIdx.x * 256 + threadIdx.x;
    float4 v = reinterpret_cast<const float4*>(enc_out)[i];
    bf16 h0, l0, h1, l1, h2, l2, h3, l3;
    splitbf(v.x, h0, l0); splitbf(v.y, h1, l1);
    splitbf(v.z, h2, l2); splitbf(v.w, h3, l3);
    __nv_bfloat162* Eh2 = reinterpret_cast<__nv_bfloat162*>(g_E_h);
    __nv_bfloat162* El2 = reinterpret_cast<__nv_bfloat162*>(g_E_l);
    Eh2[i * 2 + 0] = __nv_bfloat162(h0, h1);
    Eh2[i * 2 + 1] = __nv_bfloat162(h2, h3);
    El2[i * 2 + 0] = __nv_bfloat162(l0, l1);
    El2[i * 2 + 1] = __nv_bfloat162(l2, l3);
    __half2* E162 = reinterpret_cast<__half2*>(g_E16);
    E162[i * 2 + 0] = __half2(__float2half_rn(v.x), __float2half_rn(v.y));
    E162[i * 2 + 1] = __half2(__float2half_rn(v.z), __float2half_rn(v.w));
}

__global__ void mean_kernel(const float* __restrict__ enc_out) {
    int idx = blockIdx.x * 256 + threadIdx.x;
    int b = idx / ENC, e = idx % ENC;
    const float* src = enc_out + (size_t)b * P * ENC + e;
    float s = 0.f;
#pragma unroll 4
    for (int p = 0; p < P; p++) s += src[(size_t)p * ENC];
    splitbf(s * (1.f / 196.f), g_mean_h[idx], g_mean_l[idx]);
}

__global__ void split_hc() {
    int idx = blockIdx.x * 256 + threadIdx.x;
    int b = idx / DEC, d = idx % DEC;
    splitbf(g_hc[b * 2 * DEC + d], g_h_h[idx], g_h_l[idx]);
    g_c[idx] = g_hc[b * 2 * DEC + DEC + d];
}

// -------------------------- per-step kernels --------------------------------
// Fused embed + scores + softmax: one block per batch row.
__global__ void __launch_bounds__(256)
scores_softmax_kernel(const float* __restrict__ emb,
                      const int* __restrict__ cap,
                      const float* __restrict__ w_att,
                      const float* __restrict__ b_att, int t) {
    __shared__ float s_dec[ATT];
    __shared__ float s_w[ATT];
    __shared__ float s_sc[P];
    __shared__ float red[256];
    int b = blockIdx.x, tid = threadIdx.x;
    int warp = tid >> 5, lane = tid & 31;

    if (tid < 128) {       // embed copy -> x[b, 0:EMB] planes
        int cidx = cap[b * T + t];
        float4 v = reinterpret_cast<const float4*>(
            emb + (size_t)cidx * EMB)[tid];
        int o = b * XDIM + tid * 4;
        splitbf(v.x, g_x_h[o + 0], g_x_l[o + 0]);
        splitbf(v.y, g_x_h[o + 1], g_x_l[o + 1]);
        splitbf(v.z, g_x_h[o + 2], g_x_l[o + 2]);
        splitbf(v.w, g_x_h[o + 3], g_x_l[o + 3]);
    }
    for (int i = tid; i < ATT; i += 256) {
        s_dec[i] = g_hall[b * HALLN + i];
        s_w[i]   = w_att[i];
    }
    __syncthreads();
    float batt = b_att[0];
    for (int p = warp; p < P; p += 8) {
        const float* ep = &g_encproj[((size_t)(b * P + p)) * ATT];
        float s = 0.f;
#pragma unroll 4
        for (int a = lane; a < ATT; a += 32) {
            float e = ep[a] + s_dec[a];
            s += fmaxf(e, 0.f) * s_w[a];
        }
#pragma unroll
        for (int o = 16; o; o >>= 1) s += __shfl_down_sync(0xffffffffu, s, o);
        if (lane == 0) s_sc[p] = s + batt;
    }
    __syncthreads();
    float v = (tid < P) ? s_sc[tid] : -1e30f;
    red[tid] = v;
    __syncthreads();
    for (int o = 128; o; o >>= 1) {
        if (tid < o) red[tid] = fmaxf(red[tid], red[tid + o]);
        __syncthreads();
    }
    float m = red[0];
    __syncthreads();
    float e = (tid < P) ? expf(v - m) : 0.f;
    red[tid] = e;
    __syncthreads();
    for (int o = 128; o; o >>= 1) {
        if (tid < o) red[tid] += red[tid + o];
        __syncthreads();
    }
    if (tid < P) g_alpha[b * P + tid] = e / red[0];
}

// x[b, EMB+ch] = sigmoid(fbeta) * sum_p alpha[b,p]*E16[b,p,ch]   (fp16-hi
// read: halves the dominant per-step DRAM stream; eps=2^-11 -> final ~4e-4)
__global__ void context_kernel() {
    __shared__ float s_a[P];
    int b = blockIdx.x, tid = threadIdx.x;
    int ch = blockIdx.y * 512 + tid * 2;
    if (tid < P) s_a[tid] = g_alpha[b * P + tid];
    __syncthreads();
    const __half* base = g_E16 + (size_t)b * P * ENC + ch;
    float ax = 0.f, ay = 0.f;
#pragma unroll 4
    for (int p = 0; p < P; p++) {
        __half2 v = *reinterpret_cast<const __half2*>(base + (size_t)p * ENC);
        float a = s_a[p];
        ax = fmaf(a, __half2float(v.x), ax);
        ay = fmaf(a, __half2float(v.y), ay);
    }
    float g0 = 1.f / (1.f + expf(-g_hall[b * HALLN + ATT + ch]));
    float g1 = 1.f / (1.f + expf(-g_hall[b * HALLN + ATT + ch + 1]));
    int o = b * XDIM + EMB + ch;
    splitbf(g0 * ax, g_x_h[o], g_x_l[o]);
    splitbf(g1 * ay, g_x_h[o + 1], g_x_l[o + 1]);
}

// Deterministic split-K reduce + LSTM cell; writes h planes + c.
__global__ void lstm_kernel() {
    int idx = blockIdx.x * 256 + threadIdx.x;
    int b = idx / DEC, d = idx % DEC;
    const float* hallg = &g_hall[b * HALLN + ATT + ENC];
    float gi = hallg[d];
    float gf = hallg[DEC + d];
    float gg = hallg[2 * DEC + d];
    float go = hallg[3 * DEC + d];
#pragma unroll
    for (int s = 0; s < KSPLIT; s++) {
        const float* pp = &g_gpart[((size_t)s * B + b) * G4];
        gi += pp[d];
        gf += pp[DEC + d];
        gg += pp[2 * DEC + d];
        go += pp[3 * DEC + d];
    }
    float c  = g_c[idx];
    float si = 1.f / (1.f + expf(-gi));
    float sf = 1.f / (1.f + expf(-gf));
    float so = 1.f / (1.f + expf(-go));
    float cn = sf * c + si * tanhf(gg);
    float hn = so * tanhf(cn);
    g_c[idx] = cn;
    splitbf(hn, g_h_h[idx], g_h_l[idx]);
}

// ------------------------------- launcher -----------------------------------
extern "C" void kernel_launch(void* const* d_in, const int* in_sizes, int n_in,
                              void* d_out, int out_size) {
    const float* enc_out   = (const float*)d_in[0];
    const int*   captions  = (const int*)  d_in[1];
    const float* emb       = (const float*)d_in[2];
    const float* W_init_h  = (const float*)d_in[3];
    const float* b_init_h  = (const float*)d_in[4];
    const float* W_init_c  = (const float*)d_in[5];
    const float* b_init_c  = (const float*)d_in[6];
    const float* W_enc_att = (const float*)d_in[7];
    const float* b_enc_att = (const float*)d_in[8];
    const float* W_dec_att = (const float*)d_in[9];
    const float* b_dec_att = (const float*)d_in[10];
    const float* w_att     = (const float*)d_in[11];
    const float* b_att     = (const float*)d_in[12];
    const float* W_fbeta   = (const float*)d_in[13];
    const float* b_fbeta   = (const float*)d_in[14];
    const float* W_ih      = (const float*)d_in[15];
    const float* b_ih      = (const float*)d_in[16];
    const float* W_hh      = (const float*)d_in[17];
    const float* b_hh      = (const float*)d_in[18];
    const float* W_fc      = (const float*)d_in[19];
    const float* b_fc      = (const float*)d_in[20];
    float* out = (float*)d_out;

    bf16 *pMh, *pMl, *pHh, *pHl, *pXh, *pXl, *pEh, *pEl;
    bf16 *pWencH, *pWencL, *pWinH, *pWinL, *pWcH, *pWcL, *pWihH, *pWihL;
    float *p_hc, *p_encproj, *p_hall, *p_gpart, *p_ball, *p_binit;
    cudaGetSymbolAddress((void**)&pEh, g_E_h);
    cudaGetSymbolAddress((void**)&pEl, g_E_l);
    cudaGetSymbolAddress((void**)&pMh, g_mean_h);
    cudaGetSymbolAddress((void**)&pMl, g_mean_l);
    cudaGetSymbolAddress((void**)&pHh, g_h_h);
    cudaGetSymbolAddress((void**)&pHl, g_h_l);
    cudaGetSymbolAddress((void**)&pXh, g_x_h);
    cudaGetSymbolAddress((void**)&pXl, g_x_l);
    cudaGetSymbolAddress((void**)&pWencH, g_WencT_h);
    cudaGetSymbolAddress((void**)&pWencL, g_WencT_l);
    cudaGetSymbolAddress((void**)&pWinH, g_WinitT_h);
    cudaGetSymbolAddress((void**)&pWinL, g_WinitT_l);
    cudaGetSymbolAddress((void**)&pWcH, g_WcombT_h);
    cudaGetSymbolAddress((void**)&pWcL, g_WcombT_l);
    cudaGetSymbolAddress((void**)&pWihH, g_WihT_h);
    cudaGetSymbolAddress((void**)&pWihL, g_WihT_l);
    cudaGetSymbolAddress((void**)&p_hc, g_hc);
    cudaGetSymbolAddress((void**)&p_encproj, g_encproj);
    cudaGetSymbolAddress((void**)&p_hall, g_hall);
    cudaGetSymbolAddress((void**)&p_gpart, g_gpart);
    cudaGetSymbolAddress((void**)&p_ball, g_ball);
    cudaGetSymbolAddress((void**)&p_binit, g_binit);

    cudaFuncSetAttribute(gemm_bf3<8>,
                         cudaFuncAttributeMaxDynamicSharedMemorySize, SMEM_N8);
    cudaFuncSetAttribute(gemm_bf3<4>,
                         cudaFuncAttributeMaxDynamicSharedMemorySize, SMEM_N4);

    // ---- one-time precompute: coalesced transposes ----
    dim3 tb(32, 8);
    transpose_split<<<dim3(ATT / 32, ENC / 32), tb>>>(      // W_enc_att
        W_enc_att, pWencH, pWencL, ENC, ATT);
    transpose_split<<<dim3(DEC / 32, ENC / 32), tb>>>(      // W_init_h
        W_init_h, pWinH, pWinL, ENC, DEC);
    transpose_split<<<dim3(DEC / 32, ENC / 32), tb>>>(      // W_init_c
        W_init_c, pWinH + (size_t)DEC * ENC, pWinL + (size_t)DEC * ENC, ENC,
        DEC);
    transpose_split<<<dim3(ATT / 32, DEC / 32), tb>>>(      // W_dec_att
        W_dec_att, pWcH, pWcL, DEC, ATT);
    transpose_split<<<dim3(ENC / 32, DEC / 32), tb>>>(      // W_fbeta
        W_fbeta, pWcH + (size_t)ATT * DEC, pWcL + (size_t)ATT * DEC, DEC, ENC);
    transpose_split<<<dim3(G4 / 32, DEC / 32), tb>>>(       // W_hh
        W_hh, pWcH + (size_t)(ATT + ENC) * DEC, pWcL + (size_t)(ATT + ENC) * DEC,
        DEC, G4);
    transpose_split<<<dim3((VOC + 31) / 32, DEC / 32), tb>>>(  // W_fc
        W_fc, pWcH + (size_t)HALLN * DEC, pWcL + (size_t)HALLN * DEC, DEC, VOC);
    transpose_split<<<dim3(G4 / 32, XDIM / 32), tb>>>(      // W_ih
        W_ih, pWihH, pWihL, XDIM, G4);

    pack_bias<<<(HALLN + 2 * DEC + 255) / 256, 256>>>(b_dec_att, b_fbeta, b_hh,
                                                      b_ih, b_init_h, b_init_c);
    split_encout<<<(int)(((size_t)B * P * ENC / 4 + 255) / 256), 256>>>(enc_out);

    // enc_proj = enc_out @ W_enc_att + b  -> fp32 [25088, 512]
    gemm_bf3<8><<<dim3(ATT / 128, B * P / 128, 1), 256, SMEM_N8>>>(
        pEh, pEl, pWencH, pWencL, p_encproj, nullptr, B * P, ATT, ATT, ENC,
        ATT, 0, b_enc_att, nullptr, ENC);

    mean_kernel<<<B * ENC / 256, 256>>>(enc_out);

    // [h0|c0] = mean @ [W_init_h|W_init_c] + b
    gemm_bf3<8><<<dim3(2 * DEC / 128, 1, 1), 256, SMEM_N8>>>(
        pMh, pMl, pWinH, pWinL, p_hc, nullptr, B, 2 * DEC, 2 * DEC, ENC,
        2 * DEC, 0, p_binit, nullptr, ENC);
    split_hc<<<B * DEC / 256, 256>>>();

    // hall(0) = h0 @ Wall + ball
    gemm_bf3<8><<<dim3(HALLN / 128, 1, 1), 256, SMEM_N8>>>(
        pHh, pHl, pWcH, pWcL, p_hall, nullptr, B, HALLN, HALLN, DEC, HALLN, 0,
        p_ball, nullptr, DEC);

    // ---- decode loop ----
    for (int t = 0; t < NSTEP; t++) {
        scores_softmax_kernel<<<B, 256>>>(emb, captions, w_att, b_att, t);
        context_kernel<<<dim3(B, ENC / 512), 256>>>();

        // gates partials = x @ W_ih, split-K over XDIM (16 chunks, 256 CTAs)
        gemm_bf3<8><<<dim3(G4 / 128, 1, KSPLIT), 256, SMEM_N8>>>(
            pXh, pXl, pWihH, pWihL, p_gpart, nullptr, B, G4, G4, XDIM, G4, 0,
            nullptr, nullptr, KCHUNK);

        lstm_kernel<<<B * DEC / 256, 256>>>();

        // combined: [hall(t+1) | fc(t)] = h @ [Wall | Wfc], BN=64 -> 229 CTAs
        gemm_bf3<4><<<dim3((COMBN + 63) / 64, 1, 1), 256, SMEM_N4>>>(
            pHh, pHl, pWcH, pWcL, p_hall, out + (size_t)t * VOC, B, COMBN,
            HALLN, DEC, HALLN, NSTEP * VOC, p_ball, b_fc, DEC);
    }
}

// round 14
// speedup vs baseline: 1.5573x; 1.1195x over previous
#include <cuda_runtime.h>
#include <cuda_bf16.h>
#include <cuda_fp16.h>
#include <cstdint>
#include <cstddef>

// ---------------------------------------------------------------------------
// Show-Attend-Tell decoder. Round 13 = R12 resubmit (R11 + fp16 enc_proj):
// enc_proj computed full-precision (3-pass bf16), stored fp16 by the GEMM
// epilogue. Per-step streaming set: E16 102MB + encproj16 25MB ~ L2-resident.
// ---------------------------------------------------------------------------

constexpr int B    = 128;
constexpr int P    = 196;
constexpr int ENC  = 2048;
constexpr int EMB  = 512;
constexpr int DEC  = 512;
constexpr int ATT  = 512;
constexpr int VOC  = 10000;
constexpr int T    = 20;
constexpr int NSTEP = T - 1;           // 19
constexpr int G4   = 4 * DEC;          // 2048
constexpr int HALLN = ATT + ENC + G4;  // 4608
constexpr int COMBN = HALLN + VOC;     // 14608
constexpr int XDIM = EMB + ENC;        // 2560
constexpr int KSPLIT = 16;
constexpr int KCHUNK = XDIM / KSPLIT;  // 160

using bf16 = __nv_bfloat16;

// ----------------------------- device scratch ------------------------------
__device__ float g_hc[B * 2 * DEC];
__device__ float g_c[B * DEC];
__device__ __align__(16) bf16  g_h_h[B * DEC];
__device__ __align__(16) bf16  g_h_l[B * DEC];
__device__ __align__(16) bf16  g_mean_h[B * ENC];
__device__ __align__(16) bf16  g_mean_l[B * ENC];
__device__ __align__(16) bf16  g_x_h[B * XDIM];
__device__ __align__(16) bf16  g_x_l[B * XDIM];
__device__ __align__(16) bf16  g_E_h[(size_t)B * P * ENC];
__device__ __align__(16) bf16  g_E_l[(size_t)B * P * ENC];
__device__ __align__(16) __half g_E16[(size_t)B * P * ENC];     // context-only
__device__ __align__(16) __half g_encproj[(size_t)B * P * ATT]; // fp16 (scores)
__device__ float g_hall[B * HALLN];
__device__ float g_alpha[B * P];
__device__ float g_gpart[(size_t)KSPLIT * B * G4];
// packed / transposed weights (bf16 hi/lo planes, [N][K] layout)
__device__ __align__(16) bf16 g_WencT_h[ATT * ENC];
__device__ __align__(16) bf16 g_WencT_l[ATT * ENC];
__device__ __align__(16) bf16 g_WinitT_h[2 * DEC * ENC];
__device__ __align__(16) bf16 g_WinitT_l[2 * DEC * ENC];
__device__ __align__(16) bf16 g_WcombT_h[COMBN * DEC];  // [Wall|Wfc]
__device__ __align__(16) bf16 g_WcombT_l[COMBN * DEC];
__device__ __align__(16) bf16 g_WihT_h[G4 * XDIM];
__device__ __align__(16) bf16 g_WihT_l[G4 * XDIM];
__device__ float g_ball[HALLN];
__device__ float g_binit[2 * DEC];

// ------------------------------ helpers -------------------------------------
__device__ __forceinline__ void splitbf(float x, bf16& h, bf16& l) {
    h = __float2bfloat16(x);
    l = __float2bfloat16(x - __bfloat162float(h));
}

__device__ __forceinline__ void mma_bf16(float c[4], const uint32_t a[4],
                                         const uint32_t b[2]) {
    asm volatile(
        "mma.sync.aligned.m16n8k16.row.col.f32.bf16.bf16.f32 "
        "{%0,%1,%2,%3}, {%4,%5,%6,%7}, {%8,%9}, {%0,%1,%2,%3};"
        : "+f"(c[0]), "+f"(c[1]), "+f"(c[2]), "+f"(c[3])
        : "r"(a[0]), "r"(a[1]), "r"(a[2]), "r"(a[3]), "r"(b[0]), "r"(b[1]));
}

__device__ __forceinline__ void ldsm4(uint32_t& r0, uint32_t& r1, uint32_t& r2,
                                      uint32_t& r3, uint32_t addr) {
    asm volatile(
        "ldmatrix.sync.aligned.m8n8.x4.shared.b16 {%0,%1,%2,%3}, [%4];"
        : "=r"(r0), "=r"(r1), "=r"(r2), "=r"(r3) : "r"(addr));
}

__device__ __forceinline__ void cpasync16(uint32_t dst, const void* src) {
    asm volatile("cp.async.cg.shared.global [%0], [%1], 16;"
                 :: "r"(dst), "l"(src));
}

// ------------------------------ 3xBF16 GEMM ---------------------------------
// C[M,N] = (Ah+Al)[M,K] @ (Bh+Bl)^T[N,K]. K-major bf16 operands, 3 passes.
// BM=128, BN=2*NT*8. 256 thr, 8 warps (4Mx2N), warp tile 32x(NT*8).
// cp.async double buffer + ldmatrix.x4, PADK=20.
// OUT16: Cv is __half* (single destination; N1/C2/bias2 ignored).
// Otherwise dual destination: cols < N1 -> Cv fp32 (ldc, bias);
// cols >= N1 -> C2 fp32 (ldc2, bias2).
// Split-K: z selects [z*kChunk,...), C += z*M*ldc (fp32 single-dest use only).
// Requires M%128==0, kChunk%32==0, K%8==0. N tail: B rows clamped, cols guarded.
constexpr int PADK = 20;

extern __shared__ uint32_t dynsm[];

template <int NT, bool OUT16>
__global__ void __launch_bounds__(256, 2)
gemm_bf3(const bf16* __restrict__ Ah, const bf16* __restrict__ Al,
         const bf16* __restrict__ Bh, const bf16* __restrict__ Bl,
         void* __restrict__ Cv, float* __restrict__ C2,
         int M, int N, int N1, int K, int ldc, int ldc2,
         const float* __restrict__ bias, const float* __restrict__ bias2,
         int kChunk) {
    constexpr int BN     = 2 * NT * 8;
    constexpr int APLANE = 128 * PADK;
    constexpr int BPLANE = BN * PADK;
    constexpr int STAGE  = 2 * APLANE + 2 * BPLANE;
    constexpr int BLOADS = BN / 64;

    const int tid  = threadIdx.x;
    const int warp = tid >> 5;
    const int lane = tid & 31;
    const int lr   = lane >> 2;
    const int lq   = lane & 3;
    const int wm   = warp & 3;
    const int wn   = warp >> 2;
    const int rowBase = blockIdx.y * 128;
    const int colBase = blockIdx.x * BN;
    const int k0 = blockIdx.z * kChunk;
    const int nIter = kChunk / 32;

    const uint32_t smemBase = (uint32_t)__cvta_generic_to_shared(dynsm);

    auto load_stage = [&](int it, int stg) {
        const int kb = k0 + it * 32;
        const uint32_t sb = smemBase + (uint32_t)(stg * STAGE) * 4;
#pragma unroll
        for (int i = 0; i < 2; i++) {
            int idx = tid + i * 256;
            int r = idx >> 2, ch = idx & 3;
            const size_t off = (size_t)(rowBase + r) * K + kb + ch * 8;
            const uint32_t d = (uint32_t)(r * PADK + ch * 4) * 4;
            cpasync16(sb + d,              Ah + off);
            cpasync16(sb + APLANE * 4 + d, Al + off);
        }
#pragma unroll
        for (int i = 0; i < BLOADS; i++) {
            int idx = tid + i * 256;
            int r = idx >> 2, ch = idx & 3;
            const int n = min(colBase + r, N - 1);
            const size_t off = (size_t)n * K + kb + ch * 8;
            const uint32_t d = (uint32_t)(r * PADK + ch * 4) * 4;
            cpasync16(sb + 2u * APLANE * 4 + d,            Bh + off);
            cpasync16(sb + (2u * APLANE + BPLANE) * 4 + d, Bl + off);
        }
    };

    const int aRow = (lane & 7) + ((lane >> 3) & 1) * 8;
    const int aK   = ((lane >> 4) & 1) * 4;
    const int bRow = (lane & 7) + ((lane >> 4) & 1) * 8;
    const int bK   = ((lane >> 3) & 1) * 4;

    float acc[2][NT][4];
#pragma unroll
    for (int mt = 0; mt < 2; mt++)
#pragma unroll
        for (int nt = 0; nt < NT; nt++)
#pragma unroll
            for (int j = 0; j < 4; j++) acc[mt][nt][j] = 0.f;

    load_stage(0, 0);
    asm volatile("cp.async.commit_group;");

    for (int it = 0; it < nIter; it++) {
        if (it + 1 < nIter) {
            load_stage(it + 1, (it + 1) & 1);
            asm volatile("cp.async.commit_group;");
            asm volatile("cp.async.wait_group 1;");
        } else {
            asm volatile("cp.async.wait_group 0;");
        }
        __syncthreads();

        const uint32_t sb = smemBase + (uint32_t)((it & 1) * STAGE) * 4;
#pragma unroll
        for (int s = 0; s < 2; s++) {
            const uint32_t ks = (uint32_t)(s * 8) * 4;
            uint32_t ah[2][4], al[2][4], bh[NT][2], bl[NT][2];
#pragma unroll
            for (int mt = 0; mt < 2; mt++) {
                uint32_t ra = (uint32_t)((wm * 32 + mt * 16 + aRow) * PADK +
                                         aK) * 4 + ks;
                ldsm4(ah[mt][0], ah[mt][1], ah[mt][2], ah[mt][3], sb + ra);
                ldsm4(al[mt][0], al[mt][1], al[mt][2], al[mt][3],
                      sb + APLANE * 4 + ra);
            }
#pragma unroll
            for (int np = 0; np < NT / 2; np++) {
                uint32_t rb = (uint32_t)((wn * NT * 8 + np * 16 + bRow) *
                                         PADK + bK) * 4 + ks;
                ldsm4(bh[2 * np][0], bh[2 * np][1], bh[2 * np + 1][0],
                      bh[2 * np + 1][1], sb + 2u * APLANE * 4 + rb);
                ldsm4(bl[2 * np][0], bl[2 * np][1], bl[2 * np + 1][0],
                      bl[2 * np + 1][1], sb + (2u * APLANE + BPLANE) * 4 + rb);
            }
#pragma unroll
            for (int nt = 0; nt < NT; nt++)
#pragma unroll
                for (int mt = 0; mt < 2; mt++) {
                    mma_bf16(acc[mt][nt], ah[mt], bh[nt]);
                    mma_bf16(acc[mt][nt], al[mt], bh[nt]);
                    mma_bf16(acc[mt][nt], ah[mt], bl[nt]);
                }
        }
        __syncthreads();
    }

#pragma unroll
    for (int mt = 0; mt < 2; mt++) {
        int r0 = rowBase + wm * 32 + mt * 16 + lr;
#pragma unroll
        for (int nt = 0; nt < NT; nt++) {
            int cbase = colBase + wn * NT * 8 + nt * 8 + 2 * lq;
#pragma unroll
            for (int cc = 0; cc < 2; cc++) {
                int c = cbase + cc;
                if (c >= N) continue;
                float v0 = acc[mt][nt][cc];
                float v1 = acc[mt][nt][2 + cc];
                if (OUT16) {
                    __half* C16 = (__half*)Cv;
                    float bb = bias ? bias[c] : 0.f;
                    C16[(size_t)r0 * ldc + c] = __float2half_rn(v0 + bb);
                    C16[(size_t)(r0 + 8) * ldc + c] = __float2half_rn(v1 + bb);
                } else {
                    float* C = (float*)Cv + (size_t)blockIdx.z * M * ldc;
                    if (c < N1) {
                        float bb = bias ? bias[c] : 0.f;
                        C[(size_t)r0 * ldc + c] = v0 + bb;
                        C[(size_t)(r0 + 8) * ldc + c] = v1 + bb;
                    } else {
                        int c2 = c - N1;
                        float bb = bias2 ? bias2[c2] : 0.f;
                        C2[(size_t)r0 * ldc2 + c2] = v0 + bb;
                        C2[(size_t)(r0 + 8) * ldc2 + c2] = v1 + bb;
                    }
                }
            }
        }
    }
}

constexpr int SMEM_N8 = 2 * (2 * 128 * PADK + 2 * 128 * PADK) * 4;  // 81920
constexpr int SMEM_N4 = 2 * (2 * 128 * PADK + 2 * 64  * PADK) * 4;  // 61440

// ---------------------- coalesced transpose + split --------------------------
__global__ void transpose_split(const float* __restrict__ src,
                                bf16* __restrict__ dh, bf16* __restrict__ dl,
                                int Krows, int Ncols) {
    __shared__ float tile[32][33];
    const int nb = blockIdx.x * 32, kb = blockIdx.y * 32;
    const int tx = threadIdx.x, ty = threadIdx.y;   // (32, 8)
#pragma unroll
    for (int j = 0; j < 4; j++) {
        int k = kb + ty + j * 8;
        int n = nb + tx;
        tile[ty + j * 8][tx] = (n < Ncols) ? src[(size_t)k * Ncols + n] : 0.f;
    }
    __syncthreads();
#pragma unroll
    for (int j = 0; j < 4; j++) {
        int n = nb + ty + j * 8;
        int k = kb + tx;
        if (n < Ncols) {
            bf16 h, l;
            splitbf(tile[tx][ty + j * 8], h, l);
            dh[(size_t)n * Krows + k] = h;
            dl[(size_t)n * Krows + k] = l;
        }
    }
}

// ---------------------------- other pack kernels ----------------------------
__global__ void pack_bias(const float* __restrict__ bd,
                          const float* __restrict__ bf,
                          const float* __restrict__ bhh,
                          const float* __restrict__ bih,
                          const float* __restrict__ bh0,
                          const float* __restrict__ bc0) {
    int c = blockIdx.x * 256 + threadIdx.x;
    if (c < HALLN) {
        float v;
        if (c < ATT)            v = bd[c];
        else if (c < ATT + ENC) v = bf[c - ATT];
        else                    v = bhh[c - ATT - ENC] + bih[c - ATT - ENC];
        g_ball[c] = v;
    } else if (c < HALLN + 2 * DEC) {
        int q = c - HALLN;
        g_binit[q] = (q < DEC) ? bh0[q] : bc0[q - DEC];
    }
}

__global__ void split_encout(const float* __restrict__ enc_out) {
    size_t i = (size_t)blockIdx.x * 256 + threadIdx.x;
    float4 v = reinterpret_cast<const float4*>(enc_out)[i];
    bf16 h0, l0, h1, l1, h2, l2, h3, l3;
    splitbf(v.x, h0, l0); splitbf(v.y, h1, l1);
    splitbf(v.z, h2, l2); splitbf(v.w, h3, l3);
    __nv_bfloat162* Eh2 = reinterpret_cast<__nv_bfloat162*>(g_E_h);
    __nv_bfloat162* El2 = reinterpret_cast<__nv_bfloat162*>(g_E_l);
    Eh2[i * 2 + 0] = __nv_bfloat162(h0, h1);
    Eh2[i * 2 + 1] = __nv_bfloat162(h2, h3);
    El2[i * 2 + 0] = __nv_bfloat162(l0, l1);
    El2[i * 2 + 1] = __nv_bfloat162(l2, l3);
    __half2* E162 = reinterpret_cast<__half2*>(g_E16);
    E162[i * 2 + 0] = __half2(__float2half_rn(v.x), __float2half_rn(v.y));
    E162[i * 2 + 1] = __half2(__float2half_rn(v.z), __float2half_rn(v.w));
}

__global__ void mean_kernel(const float* __restrict__ enc_out) {
    int idx = blockIdx.x * 256 + threadIdx.x;
    int b = idx / ENC, e = idx % ENC;
    const float* src = enc_out + (size_t)b * P * ENC + e;
    float s = 0.f;
#pragma unroll 4
    for (int p = 0; p < P; p++) s += src[(size_t)p * ENC];
    splitbf(s * (1.f / 196.f), g_mean_h[idx], g_mean_l[idx]);
}

__global__ void split_hc() {
    int idx = blockIdx.x * 256 + threadIdx.x;
    int b = idx / DEC, d = idx % DEC;
    splitbf(g_hc[b * 2 * DEC + d], g_h_h[idx], g_h_l[idx]);
    g_c[idx] = g_hc[b * 2 * DEC + DEC + d];
}

// -------------------------- per-step kernels --------------------------------
// Fused embed + scores + softmax: one block per batch row; encproj in fp16.
__global__ void __launch_bounds__(256)
scores_softmax_kernel(const float* __restrict__ emb,
                      const int* __restrict__ cap,
                      const float* __restrict__ w_att,
                      const float* __restrict__ b_att, int t) {
    __shared__ float s_dec[ATT];
    __shared__ float s_w[ATT];
    __shared__ float s_sc[P];
    __shared__ float red[256];
    int b = blockIdx.x, tid = threadIdx.x;
    int warp = tid >> 5, lane = tid & 31;

    if (tid < 128) {       // embed copy -> x[b, 0:EMB] planes
        int cidx = cap[b * T + t];
        float4 v = reinterpret_cast<const float4*>(
            emb + (size_t)cidx * EMB)[tid];
        int o = b * XDIM + tid * 4;
        splitbf(v.x, g_x_h[o + 0], g_x_l[o + 0]);
        splitbf(v.y, g_x_h[o + 1], g_x_l[o + 1]);
        splitbf(v.z, g_x_h[o + 2], g_x_l[o + 2]);
        splitbf(v.w, g_x_h[o + 3], g_x_l[o + 3]);
    }
    for (int i = tid; i < ATT; i += 256) {
        s_dec[i] = g_hall[b * HALLN + i];
        s_w[i]   = w_att[i];
    }
    __syncthreads();
    float batt = b_att[0];
    for (int p = warp; p < P; p += 8) {
        const __half2* ep2 = reinterpret_cast<const __half2*>(
            g_encproj + ((size_t)(b * P + p)) * ATT);
        float s = 0.f;
#pragma unroll 4
        for (int a2 = lane; a2 < ATT / 2; a2 += 32) {
            __half2 hv = ep2[a2];
            int a = a2 * 2;
            float e0 = __half2float(hv.x) + s_dec[a];
            float e1 = __half2float(hv.y) + s_dec[a + 1];
            s += fmaxf(e0, 0.f) * s_w[a] + fmaxf(e1, 0.f) * s_w[a + 1];
        }
#pragma unroll
        for (int o = 16; o; o >>= 1) s += __shfl_down_sync(0xffffffffu, s, o);
        if (lane == 0) s_sc[p] = s + batt;
    }
    __syncthreads();
    float v = (tid < P) ? s_sc[tid] : -1e30f;
    red[tid] = v;
    __syncthreads();
    for (int o = 128; o; o >>= 1) {
        if (tid < o) red[tid] = fmaxf(red[tid], red[tid + o]);
        __syncthreads();
    }
    float m = red[0];
    __syncthreads();
    float e = (tid < P) ? expf(v - m) : 0.f;
    red[tid] = e;
    __syncthreads();
    for (int o = 128; o; o >>= 1) {
        if (tid < o) red[tid] += red[tid + o];
        __syncthreads();
    }
    if (tid < P) g_alpha[b * P + tid] = e / red[0];
}

// x[b, EMB+ch] = sigmoid(fbeta) * sum_p alpha[b,p]*E16[b,p,ch]
__global__ void context_kernel() {
    __shared__ float s_a[P];
    int b = blockIdx.x, tid = threadIdx.x;
    int ch = blockIdx.y * 512 + tid * 2;
    if (tid < P) s_a[tid] = g_alpha[b * P + tid];
    __syncthreads();
    const __half* base = g_E16 + (size_t)b * P * ENC + ch;
    float ax = 0.f, ay = 0.f;
#pragma unroll 4
    for (int p = 0; p < P; p++) {
        __half2 v = *reinterpret_cast<const __half2*>(base + (size_t)p * ENC);
        float a = s_a[p];
        ax = fmaf(a, __half2float(v.x), ax);
        ay = fmaf(a, __half2float(v.y), ay);
    }
    float g0 = 1.f / (1.f + expf(-g_hall[b * HALLN + ATT + ch]));
    float g1 = 1.f / (1.f + expf(-g_hall[b * HALLN + ATT + ch + 1]));
    int o = b * XDIM + EMB + ch;
    splitbf(g0 * ax, g_x_h[o], g_x_l[o]);
    splitbf(g1 * ay, g_x_h[o + 1], g_x_l[o + 1]);
}

// Deterministic split-K reduce + LSTM cell; writes h planes + c.
__global__ void lstm_kernel() {
    int idx = blockIdx.x * 256 + threadIdx.x;
    int b = idx / DEC, d = idx % DEC;
    const float* hallg = &g_hall[b * HALLN + ATT + ENC];
    float gi = hallg[d];
    float gf = hallg[DEC + d];
    float gg = hallg[2 * DEC + d];
    float go = hallg[3 * DEC + d];
#pragma unroll
    for (int s = 0; s < KSPLIT; s++) {
        const float* pp = &g_gpart[((size_t)s * B + b) * G4];
        gi += pp[d];
        gf += pp[DEC + d];
        gg += pp[2 * DEC + d];
        go += pp[3 * DEC + d];
    }
    float c  = g_c[idx];
    float si = 1.f / (1.f + expf(-gi));
    float sf = 1.f / (1.f + expf(-gf));
    float so = 1.f / (1.f + expf(-go));
    float cn = sf * c + si * tanhf(gg);
    float hn = so * tanhf(cn);
    g_c[idx] = cn;
    splitbf(hn, g_h_h[idx], g_h_l[idx]);
}

// ------------------------------- launcher -----------------------------------
extern "C" void kernel_launch(void* const* d_in, const int* in_sizes, int n_in,
                              void* d_out, int out_size) {
    const float* enc_out   = (const float*)d_in[0];
    const int*   captions  = (const int*)  d_in[1];
    const float* emb       = (const float*)d_in[2];
    const float* W_init_h  = (const float*)d_in[3];
    const float* b_init_h  = (const float*)d_in[4];
    const float* W_init_c  = (const float*)d_in[5];
    const float* b_init_c  = (const float*)d_in[6];
    const float* W_enc_att = (const float*)d_in[7];
    const float* b_enc_att = (const float*)d_in[8];
    const float* W_dec_att = (const float*)d_in[9];
    const float* b_dec_att = (const float*)d_in[10];
    const float* w_att     = (const float*)d_in[11];
    const float* b_att     = (const float*)d_in[12];
    const float* W_fbeta   = (const float*)d_in[13];
    const float* b_fbeta   = (const float*)d_in[14];
    const float* W_ih      = (const float*)d_in[15];
    const float* b_ih      = (const float*)d_in[16];
    const float* W_hh      = (const float*)d_in[17];
    const float* b_hh      = (const float*)d_in[18];
    const float* W_fc      = (const float*)d_in[19];
    const float* b_fc      = (const float*)d_in[20];
    float* out = (float*)d_out;

    bf16 *pMh, *pMl, *pHh, *pHl, *pXh, *pXl, *pEh, *pEl;
    bf16 *pWencH, *pWencL, *pWinH, *pWinL, *pWcH, *pWcL, *pWihH, *pWihL;
    float *p_hc, *p_hall, *p_gpart, *p_ball, *p_binit;
    __half* p_encproj;
    cudaGetSymbolAddress((void**)&pEh, g_E_h);
    cudaGetSymbolAddress((void**)&pEl, g_E_l);
    cudaGetSymbolAddress((void**)&pMh, g_mean_h);
    cudaGetSymbolAddress((void**)&pMl, g_mean_l);
    cudaGetSymbolAddress((void**)&pHh, g_h_h);
    cudaGetSymbolAddress((void**)&pHl, g_h_l);
    cudaGetSymbolAddress((void**)&pXh, g_x_h);
    cudaGetSymbolAddress((void**)&pXl, g_x_l);
    cudaGetSymbolAddress((void**)&pWencH, g_WencT_h);
    cudaGetSymbolAddress((void**)&pWencL, g_WencT_l);
    cudaGetSymbolAddress((void**)&pWinH, g_WinitT_h);
    cudaGetSymbolAddress((void**)&pWinL, g_WinitT_l);
    cudaGetSymbolAddress((void**)&pWcH, g_WcombT_h);
    cudaGetSymbolAddress((void**)&pWcL, g_WcombT_l);
    cudaGetSymbolAddress((void**)&pWihH, g_WihT_h);
    cudaGetSymbolAddress((void**)&pWihL, g_WihT_l);
    cudaGetSymbolAddress((void**)&p_hc, g_hc);
    cudaGetSymbolAddress((void**)&p_encproj, g_encproj);
    cudaGetSymbolAddress((void**)&p_hall, g_hall);
    cudaGetSymbolAddress((void**)&p_gpart, g_gpart);
    cudaGetSymbolAddress((void**)&p_ball, g_ball);
    cudaGetSymbolAddress((void**)&p_binit, g_binit);

    cudaFuncSetAttribute(gemm_bf3<8, false>,
                         cudaFuncAttributeMaxDynamicSharedMemorySize, SMEM_N8);
    cudaFuncSetAttribute(gemm_bf3<8, true>,
                         cudaFuncAttributeMaxDynamicSharedMemorySize, SMEM_N8);
    cudaFuncSetAttribute(gemm_bf3<4, false>,
                         cudaFuncAttributeMaxDynamicSharedMemorySize, SMEM_N4);

    // ---- one-time precompute: coalesced transposes ----
    dim3 tb(32, 8);
    transpose_split<<<dim3(ATT / 32, ENC / 32), tb>>>(
        W_enc_att, pWencH, pWencL, ENC, ATT);
    transpose_split<<<dim3(DEC / 32, ENC / 32), tb>>>(
        W_init_h, pWinH, pWinL, ENC, DEC);
    transpose_split<<<dim3(DEC / 32, ENC / 32), tb>>>(
        W_init_c, pWinH + (size_t)DEC * ENC, pWinL + (size_t)DEC * ENC, ENC,
        DEC);
    transpose_split<<<dim3(ATT / 32, DEC / 32), tb>>>(
        W_dec_att, pWcH, pWcL, DEC, ATT);
    transpose_split<<<dim3(ENC / 32, DEC / 32), tb>>>(
        W_fbeta, pWcH + (size_t)ATT * DEC, pWcL + (size_t)ATT * DEC, DEC, ENC);
    transpose_split<<<dim3(G4 / 32, DEC / 32), tb>>>(
        W_hh, pWcH + (size_t)(ATT + ENC) * DEC, pWcL + (size_t)(ATT + ENC) * DEC,
        DEC, G4);
    transpose_split<<<dim3((VOC + 31) / 32, DEC / 32), tb>>>(
        W_fc, pWcH + (size_t)HALLN * DEC, pWcL + (size_t)HALLN * DEC, DEC, VOC);
    transpose_split<<<dim3(G4 / 32, XDIM / 32), tb>>>(
        W_ih, pWihH, pWihL, XDIM, G4);

    pack_bias<<<(HALLN + 2 * DEC + 255) / 256, 256>>>(b_dec_att, b_fbeta, b_hh,
                                                      b_ih, b_init_h, b_init_c);
    split_encout<<<(int)(((size_t)B * P * ENC / 4 + 255) / 256), 256>>>(enc_out);

    // enc_proj = enc_out @ W_enc_att + b  -> fp16 [25088, 512]
    gemm_bf3<8, true><<<dim3(ATT / 128, B * P / 128, 1), 256, SMEM_N8>>>(
        pEh, pEl, pWencH, pWencL, p_encproj, nullptr, B * P, ATT, ATT, ENC,
        ATT, 0, b_enc_att, nullptr, ENC);

    mean_kernel<<<B * ENC / 256, 256>>>(enc_out);

    // [h0|c0] = mean @ [W_init_h|W_init_c] + b
    gemm_bf3<8, false><<<dim3(2 * DEC / 128, 1, 1), 256, SMEM_N8>>>(
        pMh, pMl, pWinH, pWinL, p_hc, nullptr, B, 2 * DEC, 2 * DEC, ENC,
        2 * DEC, 0, p_binit, nullptr, ENC);
    split_hc<<<B * DEC / 256, 256>>>();

    // hall(0) = h0 @ Wall + ball
    gemm_bf3<8, false><<<dim3(HALLN / 128, 1, 1), 256, SMEM_N8>>>(
        pHh, pHl, pWcH, pWcL, p_hall, nullptr, B, HALLN, HALLN, DEC, HALLN, 0,
        p_ball, nullptr, DEC);

    // ---- decode loop ----
    for (int t = 0; t < NSTEP; t++) {
        scores_softmax_kernel<<<B, 256>>>(emb, captions, w_att, b_att, t);
        context_kernel<<<dim3(B, ENC / 512), 256>>>();

        // gates partials = x @ W_ih, split-K over XDIM (16 chunks, 256 CTAs)
        gemm_bf3<8, false><<<dim3(G4 / 128, 1, KSPLIT), 256, SMEM_N8>>>(
            pXh, pXl, pWihH, pWihL, p_gpart, nullptr, B, G4, G4, XDIM, G4, 0,
            nullptr, nullptr, KCHUNK);

        lstm_kernel<<<B * DEC / 256, 256>>>();

        // combined: [hall(t+1) | fc(t)] = h @ [Wall | Wfc], BN=64 -> 229 CTAs
        gemm_bf3<4, false><<<dim3((COMBN + 63) / 64, 1, 1), 256, SMEM_N4>>>(
            pHh, pHl, pWcH, pWcL, p_hall, out + (size_t)t * VOC, B, COMBN,
            HALLN, DEC, HALLN, NSTEP * VOC, p_ball, b_fc, DEC);
    }
}

// round 16
// speedup vs baseline: 1.6085x; 1.0328x over previous
#include <cuda_runtime.h>
#include <cuda_bf16.h>
#include <cuda_fp16.h>
#include <cstdint>
#include <cstddef>

// ---------------------------------------------------------------------------
// Show-Attend-Tell decoder. Round 14 = R13 +
//  - fused split+mean prologue kernel (one less 205MB pass over enc_out)
//  - 3-stage cp.async pipeline for NT=4 GEMMs (comb + gates)
//  - gates: NT=4, KSPLIT=8 (same 256 CTAs, deeper pipeline, half partial I/O)
// ---------------------------------------------------------------------------

constexpr int B    = 128;
constexpr int P    = 196;
constexpr int ENC  = 2048;
constexpr int EMB  = 512;
constexpr int DEC  = 512;
constexpr int ATT  = 512;
constexpr int VOC  = 10000;
constexpr int T    = 20;
constexpr int NSTEP = T - 1;           // 19
constexpr int G4   = 4 * DEC;          // 2048
constexpr int HALLN = ATT + ENC + G4;  // 4608
constexpr int COMBN = HALLN + VOC;     // 14608
constexpr int XDIM = EMB + ENC;        // 2560
constexpr int KSPLIT = 8;
constexpr int KCHUNK = XDIM / KSPLIT;  // 320

using bf16 = __nv_bfloat16;

// ----------------------------- device scratch ------------------------------
__device__ float g_hc[B * 2 * DEC];
__device__ float g_c[B * DEC];
__device__ __align__(16) bf16  g_h_h[B * DEC];
__device__ __align__(16) bf16  g_h_l[B * DEC];
__device__ __align__(16) bf16  g_mean_h[B * ENC];
__device__ __align__(16) bf16  g_mean_l[B * ENC];
__device__ __align__(16) bf16  g_x_h[B * XDIM];
__device__ __align__(16) bf16  g_x_l[B * XDIM];
__device__ __align__(16) bf16  g_E_h[(size_t)B * P * ENC];
__device__ __align__(16) bf16  g_E_l[(size_t)B * P * ENC];
__device__ __align__(16) __half g_E16[(size_t)B * P * ENC];     // context-only
__device__ __align__(16) __half g_encproj[(size_t)B * P * ATT]; // fp16 (scores)
__device__ float g_hall[B * HALLN];
__device__ float g_alpha[B * P];
__device__ float g_gpart[(size_t)16 * B * G4];
// packed / transposed weights (bf16 hi/lo planes, [N][K] layout)
__device__ __align__(16) bf16 g_WencT_h[ATT * ENC];
__device__ __align__(16) bf16 g_WencT_l[ATT * ENC];
__device__ __align__(16) bf16 g_WinitT_h[2 * DEC * ENC];
__device__ __align__(16) bf16 g_WinitT_l[2 * DEC * ENC];
__device__ __align__(16) bf16 g_WcombT_h[COMBN * DEC];  // [Wall|Wfc]
__device__ __align__(16) bf16 g_WcombT_l[COMBN * DEC];
__device__ __align__(16) bf16 g_WihT_h[G4 * XDIM];
__device__ __align__(16) bf16 g_WihT_l[G4 * XDIM];
__device__ float g_ball[HALLN];
__device__ float g_binit[2 * DEC];

// ------------------------------ helpers -------------------------------------
__device__ __forceinline__ void splitbf(float x, bf16& h, bf16& l) {
    h = __float2bfloat16(x);
    l = __float2bfloat16(x - __bfloat162float(h));
}

__device__ __forceinline__ void mma_bf16(float c[4], const uint32_t a[4],
                                         const uint32_t b[2]) {
    asm volatile(
        "mma.sync.aligned.m16n8k16.row.col.f32.bf16.bf16.f32 "
        "{%0,%1,%2,%3}, {%4,%5,%6,%7}, {%8,%9}, {%0,%1,%2,%3};"
        : "+f"(c[0]), "+f"(c[1]), "+f"(c[2]), "+f"(c[3])
        : "r"(a[0]), "r"(a[1]), "r"(a[2]), "r"(a[3]), "r"(b[0]), "r"(b[1]));
}

__device__ __forceinline__ void ldsm4(uint32_t& r0, uint32_t& r1, uint32_t& r2,
                                      uint32_t& r3, uint32_t addr) {
    asm volatile(
        "ldmatrix.sync.aligned.m8n8.x4.shared.b16 {%0,%1,%2,%3}, [%4];"
        : "=r"(r0), "=r"(r1), "=r"(r2), "=r"(r3) : "r"(addr));
}

__device__ __forceinline__ void cpasync16(uint32_t dst, const void* src) {
    asm volatile("cp.async.cg.shared.global [%0], [%1], 16;"
                 :: "r"(dst), "l"(src));
}

// ------------------------------ 3xBF16 GEMM ---------------------------------
// C[M,N] = (Ah+Al)[M,K] @ (Bh+Bl)^T[N,K]. K-major bf16 operands, 3 passes.
// BM=128, BN=2*NT*8. 256 thr, 8 warps (4Mx2N), warp tile 32x(NT*8).
// cp.async STAGES-deep pipeline + ldmatrix.x4, PADK=20.
// OUT16: Cv is __half* (single destination; N1/C2/bias2 ignored).
// Otherwise dual destination: cols < N1 -> Cv fp32 (ldc, bias);
// cols >= N1 -> C2 fp32 (ldc2, bias2).
// Split-K: z selects [z*kChunk,...), C += z*M*ldc (fp32 single-dest use only).
// Requires M%128==0, kChunk%32==0, K%8==0, nIter>=2. N tail: rows clamped,
// cols guarded.
constexpr int PADK = 20;

extern __shared__ uint32_t dynsm[];

template <int NT, bool OUT16, int STAGES>
__global__ void __launch_bounds__(256, 2)
gemm_bf3(const bf16* __restrict__ Ah, const bf16* __restrict__ Al,
         const bf16* __restrict__ Bh, const bf16* __restrict__ Bl,
         void* __restrict__ Cv, float* __restrict__ C2,
         int M, int N, int N1, int K, int ldc, int ldc2,
         const float* __restrict__ bias, const float* __restrict__ bias2,
         int kChunk) {
    constexpr int BN     = 2 * NT * 8;
    constexpr int APLANE = 128 * PADK;
    constexpr int BPLANE = BN * PADK;
    constexpr int STAGE  = 2 * APLANE + 2 * BPLANE;
    constexpr int BLOADS = BN / 64;

    const int tid  = threadIdx.x;
    const int warp = tid >> 5;
    const int lane = tid & 31;
    const int lr   = lane >> 2;
    const int lq   = lane & 3;
    const int wm   = warp & 3;
    const int wn   = warp >> 2;
    const int rowBase = blockIdx.y * 128;
    const int colBase = blockIdx.x * BN;
    const int k0 = blockIdx.z * kChunk;
    const int nIter = kChunk / 32;

    const uint32_t smemBase = (uint32_t)__cvta_generic_to_shared(dynsm);

    auto load_stage = [&](int it, int stg) {
        const int kb = k0 + it * 32;
        const uint32_t sb = smemBase + (uint32_t)(stg * STAGE) * 4;
#pragma unroll
        for (int i = 0; i < 2; i++) {
            int idx = tid + i * 256;
            int r = idx >> 2, ch = idx & 3;
            const size_t off = (size_t)(rowBase + r) * K + kb + ch * 8;
            const uint32_t d = (uint32_t)(r * PADK + ch * 4) * 4;
            cpasync16(sb + d,              Ah + off);
            cpasync16(sb + APLANE * 4 + d, Al + off);
        }
#pragma unroll
        for (int i = 0; i < BLOADS; i++) {
            int idx = tid + i * 256;
            int r = idx >> 2, ch = idx & 3;
            const int n = min(colBase + r, N - 1);
            const size_t off = (size_t)n * K + kb + ch * 8;
            const uint32_t d = (uint32_t)(r * PADK + ch * 4) * 4;
            cpasync16(sb + 2u * APLANE * 4 + d,            Bh + off);
            cpasync16(sb + (2u * APLANE + BPLANE) * 4 + d, Bl + off);
        }
    };

    const int aRow = (lane & 7) + ((lane >> 3) & 1) * 8;
    const int aK   = ((lane >> 4) & 1) * 4;
    const int bRow = (lane & 7) + ((lane >> 4) & 1) * 8;
    const int bK   = ((lane >> 3) & 1) * 4;

    float acc[2][NT][4];
#pragma unroll
    for (int mt = 0; mt < 2; mt++)
#pragma unroll
        for (int nt = 0; nt < NT; nt++)
#pragma unroll
            for (int j = 0; j < 4; j++) acc[mt][nt][j] = 0.f;

    // prologue: fill STAGES-1 stages
    load_stage(0, 0);
    asm volatile("cp.async.commit_group;");
    if (STAGES == 3) {
        load_stage(1, 1);
        asm volatile("cp.async.commit_group;");
    }

    for (int it = 0; it < nIter; it++) {
        if (STAGES == 2) {
            if (it + 1 < nIter) {
                load_stage(it + 1, (it + 1) & 1);
                asm volatile("cp.async.commit_group;");
                asm volatile("cp.async.wait_group 1;");
            } else {
                asm volatile("cp.async.wait_group 0;");
            }
        } else {
            if (it + 2 < nIter) {
                load_stage(it + 2, (it + 2) % 3);
                asm volatile("cp.async.commit_group;");
                asm volatile("cp.async.wait_group 2;");
            } else if (it + 1 < nIter) {
                asm volatile("cp.async.wait_group 1;");
            } else {
                asm volatile("cp.async.wait_group 0;");
            }
        }
        __syncthreads();

        const int stg = (STAGES == 2) ? (it & 1) : (it % 3);
        const uint32_t sb = smemBase + (uint32_t)(stg * STAGE) * 4;
#pragma unroll
        for (int s = 0; s < 2; s++) {
            const uint32_t ks = (uint32_t)(s * 8) * 4;
            uint32_t ah[2][4], al[2][4], bh[NT][2], bl[NT][2];
#pragma unroll
            for (int mt = 0; mt < 2; mt++) {
                uint32_t ra = (uint32_t)((wm * 32 + mt * 16 + aRow) * PADK +
                                         aK) * 4 + ks;
                ldsm4(ah[mt][0], ah[mt][1], ah[mt][2], ah[mt][3], sb + ra);
                ldsm4(al[mt][0], al[mt][1], al[mt][2], al[mt][3],
                      sb + APLANE * 4 + ra);
            }
#pragma unroll
            for (int np = 0; np < NT / 2; np++) {
                uint32_t rb = (uint32_t)((wn * NT * 8 + np * 16 + bRow) *
                                         PADK + bK) * 4 + ks;
                ldsm4(bh[2 * np][0], bh[2 * np][1], bh[2 * np + 1][0],
                      bh[2 * np + 1][1], sb + 2u * APLANE * 4 + rb);
                ldsm4(bl[2 * np][0], bl[2 * np][1], bl[2 * np + 1][0],
                      bl[2 * np + 1][1], sb + (2u * APLANE + BPLANE) * 4 + rb);
            }
#pragma unroll
            for (int nt = 0; nt < NT; nt++)
#pragma unroll
                for (int mt = 0; mt < 2; mt++) {
                    mma_bf16(acc[mt][nt], ah[mt], bh[nt]);
                    mma_bf16(acc[mt][nt], al[mt], bh[nt]);
                    mma_bf16(acc[mt][nt], ah[mt], bl[nt]);
                }
        }
        __syncthreads();
    }

#pragma unroll
    for (int mt = 0; mt < 2; mt++) {
        int r0 = rowBase + wm * 32 + mt * 16 + lr;
#pragma unroll
        for (int nt = 0; nt < NT; nt++) {
            int cbase = colBase + wn * NT * 8 + nt * 8 + 2 * lq;
#pragma unroll
            for (int cc = 0; cc < 2; cc++) {
                int c = cbase + cc;
                if (c >= N) continue;
                float v0 = acc[mt][nt][cc];
                float v1 = acc[mt][nt][2 + cc];
                if (OUT16) {
                    __half* C16 = (__half*)Cv;
                    float bb = bias ? bias[c] : 0.f;
                    C16[(size_t)r0 * ldc + c] = __float2half_rn(v0 + bb);
                    C16[(size_t)(r0 + 8) * ldc + c] = __float2half_rn(v1 + bb);
                } else {
                    float* C = (float*)Cv + (size_t)blockIdx.z * M * ldc;
                    if (c < N1) {
                        float bb = bias ? bias[c] : 0.f;
                        C[(size_t)r0 * ldc + c] = v0 + bb;
                        C[(size_t)(r0 + 8) * ldc + c] = v1 + bb;
                    } else {
                        int c2 = c - N1;
                        float bb = bias2 ? bias2[c2] : 0.f;
                        C2[(size_t)r0 * ldc2 + c2] = v0 + bb;
                        C2[(size_t)(r0 + 8) * ldc2 + c2] = v1 + bb;
                    }
                }
            }
        }
    }
}

constexpr int SMEM_N8_2 = 2 * (2 * 128 * PADK + 2 * 128 * PADK) * 4;  // 81920
constexpr int SMEM_N4_3 = 3 * (2 * 128 * PADK + 2 * 64  * PADK) * 4;  // 92160

// ---------------------- coalesced transpose + split --------------------------
__global__ void transpose_split(const float* __restrict__ src,
                                bf16* __restrict__ dh, bf16* __restrict__ dl,
                                int Krows, int Ncols) {
    __shared__ float tile[32][33];
    const int nb = blockIdx.x * 32, kb = blockIdx.y * 32;
    const int tx = threadIdx.x, ty = threadIdx.y;   // (32, 8)
#pragma unroll
    for (int j = 0; j < 4; j++) {
        int k = kb + ty + j * 8;
        int n = nb + tx;
        tile[ty + j * 8][tx] = (n < Ncols) ? src[(size_t)k * Ncols + n] : 0.f;
    }
    __syncthreads();
#pragma unroll
    for (int j = 0; j < 4; j++) {
        int n = nb + ty + j * 8;
        int k = kb + tx;
        if (n < Ncols) {
            bf16 h, l;
            splitbf(tile[tx][ty + j * 8], h, l);
            dh[(size_t)n * Krows + k] = h;
            dl[(size_t)n * Krows + k] = l;
        }
    }
}

// ---------------------------- other pack kernels ----------------------------
__global__ void pack_bias(const float* __restrict__ bd,
                          const float* __restrict__ bf,
                          const float* __restrict__ bhh,
                          const float* __restrict__ bih,
                          const float* __restrict__ bh0,
                          const float* __restrict__ bc0) {
    int c = blockIdx.x * 256 + threadIdx.x;
    if (c < HALLN) {
        float v;
        if (c < ATT)            v = bd[c];
        else if (c < ATT + ENC) v = bf[c - ATT];
        else                    v = bhh[c - ATT - ENC] + bih[c - ATT - ENC];
        g_ball[c] = v;
    } else if (c < HALLN + 2 * DEC) {
        int q = c - HALLN;
        g_binit[q] = (q < DEC) ? bh0[q] : bc0[q - DEC];
    }
}

// Fused: split enc_out into bf16 hi/lo + fp16 planes AND compute the
// per-(b,channel) mean over P in the same pass (one 205MB read total).
__global__ void split_mean_kernel(const float* __restrict__ enc_out) {
    const int b  = blockIdx.x;
    const int ch = blockIdx.y * 256 + threadIdx.x;
    const float* src = enc_out + (size_t)b * P * ENC + ch;
    bf16*  Eh = g_E_h + (size_t)b * P * ENC + ch;
    bf16*  El = g_E_l + (size_t)b * P * ENC + ch;
    __half* E16 = g_E16 + (size_t)b * P * ENC + ch;
    float acc = 0.f;
#pragma unroll 4
    for (int p = 0; p < P; p++) {
        float v = src[(size_t)p * ENC];
        acc += v;
        bf16 h, l;
        splitbf(v, h, l);
        Eh[(size_t)p * ENC] = h;
        El[(size_t)p * ENC] = l;
        E16[(size_t)p * ENC] = __float2half_rn(v);
    }
    splitbf(acc * (1.f / 196.f), g_mean_h[b * ENC + ch],
            g_mean_l[b * ENC + ch]);
}

__global__ void split_hc() {
    int idx = blockIdx.x * 256 + threadIdx.x;
    int b = idx / DEC, d = idx % DEC;
    splitbf(g_hc[b * 2 * DEC + d], g_h_h[idx], g_h_l[idx]);
    g_c[idx] = g_hc[b * 2 * DEC + DEC + d];
}

// -------------------------- per-step kernels --------------------------------
// Fused embed + scores + softmax: one block per batch row; encproj in fp16.
__global__ void __launch_bounds__(256)
scores_softmax_kernel(const float* __restrict__ emb,
                      const int* __restrict__ cap,
                      const float* __restrict__ w_att,
                      const float* __restrict__ b_att, int t) {
    __shared__ float s_dec[ATT];
    __shared__ float s_w[ATT];
    __shared__ float s_sc[P];
    __shared__ float red[256];
    int b = blockIdx.x, tid = threadIdx.x;
    int warp = tid >> 5, lane = tid & 31;

    if (tid < 128) {       // embed copy -> x[b, 0:EMB] planes
        int cidx = cap[b * T + t];
        float4 v = reinterpret_cast<const float4*>(
            emb + (size_t)cidx * EMB)[tid];
        int o = b * XDIM + tid * 4;
        splitbf(v.x, g_x_h[o + 0], g_x_l[o + 0]);
        splitbf(v.y, g_x_h[o + 1], g_x_l[o + 1]);
        splitbf(v.z, g_x_h[o + 2], g_x_l[o + 2]);
        splitbf(v.w, g_x_h[o + 3], g_x_l[o + 3]);
    }
    for (int i = tid; i < ATT; i += 256) {
        s_dec[i] = g_hall[b * HALLN + i];
        s_w[i]   = w_att[i];
    }
    __syncthreads();
    float batt = b_att[0];
    for (int p = warp; p < P; p += 8) {
        const __half2* ep2 = reinterpret_cast<const __half2*>(
            g_encproj + ((size_t)(b * P + p)) * ATT);
        float s = 0.f;
#pragma unroll 4
        for (int a2 = lane; a2 < ATT / 2; a2 += 32) {
            __half2 hv = ep2[a2];
            int a = a2 * 2;
            float e0 = __half2float(hv.x) + s_dec[a];
            float e1 = __half2float(hv.y) + s_dec[a + 1];
            s += fmaxf(e0, 0.f) * s_w[a] + fmaxf(e1, 0.f) * s_w[a + 1];
        }
#pragma unroll
        for (int o = 16; o; o >>= 1) s += __shfl_down_sync(0xffffffffu, s, o);
        if (lane == 0) s_sc[p] = s + batt;
    }
    __syncthreads();
    float v = (tid < P) ? s_sc[tid] : -1e30f;
    red[tid] = v;
    __syncthreads();
    for (int o = 128; o; o >>= 1) {
        if (tid < o) red[tid] = fmaxf(red[tid], red[tid + o]);
        __syncthreads();
    }
    float m = red[0];
    __syncthreads();
    float e = (tid < P) ? expf(v - m) : 0.f;
    red[tid] = e;
    __syncthreads();
    for (int o = 128; o; o >>= 1) {
        if (tid < o) red[tid] += red[tid + o];
        __syncthreads();
    }
    if (tid < P) g_alpha[b * P + tid] = e / red[0];
}

// x[b, EMB+ch] = sigmoid(fbeta) * sum_p alpha[b,p]*E16[b,p,ch]
__global__ void context_kernel() {
    __shared__ float s_a[P];
    int b = blockIdx.x, tid = threadIdx.x;
    int ch = blockIdx.y * 512 + tid * 2;
    if (tid < P) s_a[tid] = g_alpha[b * P + tid];
    __syncthreads();
    const __half* base = g_E16 + (size_t)b * P * ENC + ch;
    float ax = 0.f, ay = 0.f;
#pragma unroll 4
    for (int p = 0; p < P; p++) {
        __half2 v = *reinterpret_cast<const __half2*>(base + (size_t)p * ENC);
        float a = s_a[p];
        ax = fmaf(a, __half2float(v.x), ax);
        ay = fmaf(a, __half2float(v.y), ay);
    }
    float g0 = 1.f / (1.f + expf(-g_hall[b * HALLN + ATT + ch]));
    float g1 = 1.f / (1.f + expf(-g_hall[b * HALLN + ATT + ch + 1]));
    int o = b * XDIM + EMB + ch;
    splitbf(g0 * ax, g_x_h[o], g_x_l[o]);
    splitbf(g1 * ay, g_x_h[o + 1], g_x_l[o + 1]);
}

// Deterministic split-K reduce + LSTM cell; writes h planes + c.
__global__ void lstm_kernel() {
    int idx = blockIdx.x * 256 + threadIdx.x;
    int b = idx / DEC, d = idx % DEC;
    const float* hallg = &g_hall[b * HALLN + ATT + ENC];
    float gi = hallg[d];
    float gf = hallg[DEC + d];
    float gg = hallg[2 * DEC + d];
    float go = hallg[3 * DEC + d];
#pragma unroll
    for (int s = 0; s < KSPLIT; s++) {
        const float* pp = &g_gpart[((size_t)s * B + b) * G4];
        gi += pp[d];
        gf += pp[DEC + d];
        gg += pp[2 * DEC + d];
        go += pp[3 * DEC + d];
    }
    float c  = g_c[idx];
    float si = 1.f / (1.f + expf(-gi));
    float sf = 1.f / (1.f + expf(-gf));
    float so = 1.f / (1.f + expf(-go));
    float cn = sf * c + si * tanhf(gg);
    float hn = so * tanhf(cn);
    g_c[idx] = cn;
    splitbf(hn, g_h_h[idx], g_h_l[idx]);
}

// ------------------------------- launcher -----------------------------------
extern "C" void kernel_launch(void* const* d_in, const int* in_sizes, int n_in,
                              void* d_out, int out_size) {
    const float* enc_out   = (const float*)d_in[0];
    const int*   captions  = (const int*)  d_in[1];
    const float* emb       = (const float*)d_in[2];
    const float* W_init_h  = (const float*)d_in[3];
    const float* b_init_h  = (const float*)d_in[4];
    const float* W_init_c  = (const float*)d_in[5];
    const float* b_init_c  = (const float*)d_in[6];
    const float* W_enc_att = (const float*)d_in[7];
    const float* b_enc_att = (const float*)d_in[8];
    const float* W_dec_att = (const float*)d_in[9];
    const float* b_dec_att = (const float*)d_in[10];
    const float* w_att     = (const float*)d_in[11];
    const float* b_att     = (const float*)d_in[12];
    const float* W_fbeta   = (const float*)d_in[13];
    const float* b_fbeta   = (const float*)d_in[14];
    const float* W_ih      = (const float*)d_in[15];
    const float* b_ih      = (const float*)d_in[16];
    const float* W_hh      = (const float*)d_in[17];
    const float* b_hh      = (const float*)d_in[18];
    const float* W_fc      = (const float*)d_in[19];
    const float* b_fc      = (const float*)d_in[20];
    float* out = (float*)d_out;

    bf16 *pMh, *pMl, *pHh, *pHl, *pXh, *pXl, *pEh, *pEl;
    bf16 *pWencH, *pWencL, *pWinH, *pWinL, *pWcH, *pWcL, *pWihH, *pWihL;
    float *p_hc, *p_hall, *p_gpart, *p_ball, *p_binit;
    __half* p_encproj;
    cudaGetSymbolAddress((void**)&pEh, g_E_h);
    cudaGetSymbolAddress((void**)&pEl, g_E_l);
    cudaGetSymbolAddress((void**)&pMh, g_mean_h);
    cudaGetSymbolAddress((void**)&pMl, g_mean_l);
    cudaGetSymbolAddress((void**)&pHh, g_h_h);
    cudaGetSymbolAddress((void**)&pHl, g_h_l);
    cudaGetSymbolAddress((void**)&pXh, g_x_h);
    cudaGetSymbolAddress((void**)&pXl, g_x_l);
    cudaGetSymbolAddress((void**)&pWencH, g_WencT_h);
    cudaGetSymbolAddress((void**)&pWencL, g_WencT_l);
    cudaGetSymbolAddress((void**)&pWinH, g_WinitT_h);
    cudaGetSymbolAddress((void**)&pWinL, g_WinitT_l);
    cudaGetSymbolAddress((void**)&pWcH, g_WcombT_h);
    cudaGetSymbolAddress((void**)&pWcL, g_WcombT_l);
    cudaGetSymbolAddress((void**)&pWihH, g_WihT_h);
    cudaGetSymbolAddress((void**)&pWihL, g_WihT_l);
    cudaGetSymbolAddress((void**)&p_hc, g_hc);
    cudaGetSymbolAddress((void**)&p_encproj, g_encproj);
    cudaGetSymbolAddress((void**)&p_hall, g_hall);
    cudaGetSymbolAddress((void**)&p_gpart, g_gpart);
    cudaGetSymbolAddress((void**)&p_ball, g_ball);
    cudaGetSymbolAddress((void**)&p_binit, g_binit);

    cudaFuncSetAttribute(gemm_bf3<8, false, 2>,
                         cudaFuncAttributeMaxDynamicSharedMemorySize,
                         SMEM_N8_2);
    cudaFuncSetAttribute(gemm_bf3<8, true, 2>,
                         cudaFuncAttributeMaxDynamicSharedMemorySize,
                         SMEM_N8_2);
    cudaFuncSetAttribute(gemm_bf3<4, false, 3>,
                         cudaFuncAttributeMaxDynamicSharedMemorySize,
                         SMEM_N4_3);

    // ---- one-time precompute: coalesced transposes ----
    dim3 tb(32, 8);
    transpose_split<<<dim3(ATT / 32, ENC / 32), tb>>>(
        W_enc_att, pWencH, pWencL, ENC, ATT);
    transpose_split<<<dim3(DEC / 32, ENC / 32), tb>>>(
        W_init_h, pWinH, pWinL, ENC, DEC);
    transpose_split<<<dim3(DEC / 32, ENC / 32), tb>>>(
        W_init_c, pWinH + (size_t)DEC * ENC, pWinL + (size_t)DEC * ENC, ENC,
        DEC);
    transpose_split<<<dim3(ATT / 32, DEC / 32), tb>>>(
        W_dec_att, pWcH, pWcL, DEC, ATT);
    transpose_split<<<dim3(ENC / 32, DEC / 32), tb>>>(
        W_fbeta, pWcH + (size_t)ATT * DEC, pWcL + (size_t)ATT * DEC, DEC, ENC);
    transpose_split<<<dim3(G4 / 32, DEC / 32), tb>>>(
        W_hh, pWcH + (size_t)(ATT + ENC) * DEC, pWcL + (size_t)(ATT + ENC) * DEC,
        DEC, G4);
    transpose_split<<<dim3((VOC + 31) / 32, DEC / 32), tb>>>(
        W_fc, pWcH + (size_t)HALLN * DEC, pWcL + (size_t)HALLN * DEC, DEC, VOC);
    transpose_split<<<dim3(G4 / 32, XDIM / 32), tb>>>(
        W_ih, pWihH, pWihL, XDIM, G4);

    pack_bias<<<(HALLN + 2 * DEC + 255) / 256, 256>>>(b_dec_att, b_fbeta, b_hh,
                                                      b_ih, b_init_h, b_init_c);
    // fused split + mean (single pass over enc_out)
    split_mean_kernel<<<dim3(B, ENC / 256), 256>>>(enc_out);

    // enc_proj = enc_out @ W_enc_att + b  -> fp16 [25088, 512]
    gemm_bf3<8, true, 2><<<dim3(ATT / 128, B * P / 128, 1), 256, SMEM_N8_2>>>(
        pEh, pEl, pWencH, pWencL, p_encproj, nullptr, B * P, ATT, ATT, ENC,
        ATT, 0, b_enc_att, nullptr, ENC);

    // [h0|c0] = mean @ [W_init_h|W_init_c] + b
    gemm_bf3<8, false, 2><<<dim3(2 * DEC / 128, 1, 1), 256, SMEM_N8_2>>>(
        pMh, pMl, pWinH, pWinL, p_hc, nullptr, B, 2 * DEC, 2 * DEC, ENC,
        2 * DEC, 0, p_binit, nullptr, ENC);
    split_hc<<<B * DEC / 256, 256>>>();

    // hall(0) = h0 @ Wall + ball
    gemm_bf3<8, false, 2><<<dim3(HALLN / 128, 1, 1), 256, SMEM_N8_2>>>(
        pHh, pHl, pWcH, pWcL, p_hall, nullptr, B, HALLN, HALLN, DEC, HALLN, 0,
        p_ball, nullptr, DEC);

    // ---- decode loop ----
    for (int t = 0; t < NSTEP; t++) {
        scores_softmax_kernel<<<B, 256>>>(emb, captions, w_att, b_att, t);
        context_kernel<<<dim3(B, ENC / 512), 256>>>();

        // gates partials = x @ W_ih, split-K (8 chunks x 32 col-blocks = 256
        // CTAs), NT=4 3-stage pipeline
        gemm_bf3<4, false, 3><<<dim3(G4 / 64, 1, KSPLIT), 256, SMEM_N4_3>>>(
            pXh, pXl, pWihH, pWihL, p_gpart, nullptr, B, G4, G4, XDIM, G4, 0,
            nullptr, nullptr, KCHUNK);

        lstm_kernel<<<B * DEC / 256, 256>>>();

        // combined: [hall(t+1) | fc(t)] = h @ [Wall | Wfc], BN=64, 3-stage
        gemm_bf3<4, false, 3><<<dim3((COMBN + 63) / 64, 1, 1), 256,
                                SMEM_N4_3>>>(
            pHh, pHl, pWcH, pWcL, p_hall, out + (size_t)t * VOC, B, COMBN,
            HALLN, DEC, HALLN, NSTEP * VOC, p_ball, b_fc, DEC);
    }
}